// round 8
// baseline (speedup 1.0000x reference)
#include <cuda_runtime.h>
#include <math.h>
#include <stdint.h>

// ---------------------------------------------------------------------------
// TSRNet 4-bit fake-quant CNN — reference-order fp32 FMA implementation.
// Theory: reference (XLA) computes each conv/dot output with ONE fp32
// accumulator, FMA, reduction in canonical order: convs (kh, kw, ci-fastest)
// [NHWC canonicalization], dots k-ascending.  We replicate that exactly:
// NHWC activations, [co][r][ci] weights, strict per-accumulator FMA order.
// Monolithic kernel: 8 images/block through conv1..softmax. Static SMEM 46KB.
// ---------------------------------------------------------------------------

#define BMAX 2048
#define IMG_TILE 8

// transposed quantized weights, float4-aligned
__device__ float  g_w1T[16 * 27];            // [co][r][ci], ci=3
__device__ float4 g_w2T4[32 * 9 * 4];        // [co][r][ci4], CI=16
__device__ float4 g_w3T4[64 * 9 * 8];        // CI=32
__device__ float4 g_w4T4[128 * 9 * 16];      // CI=64
__device__ float4 g_w5T4[256 * 9 * 32];      // CI=128
__device__ float4 g_wf1q4[512 * 64];         // [n][k4], K=256
__device__ float4 g_wf2q4[43 * 128];         // K=512

// NHWC activations (values, not codes)
__device__ float4 g_a1[BMAX * 1024];  // [img][256 sp][16ci] /4
__device__ float4 g_a2[BMAX * 512];   // [img][64][32]/4
__device__ float4 g_a3[BMAX * 256];   // [img][16][64]/4
__device__ float4 g_a4[BMAX * 128];   // [img][4][128]/4

__device__ __forceinline__ float qval_relu(float y, float s) {
    float u = __fdiv_rn(y, s);
    float k = rintf(u);
    k = fminf(fmaxf(k, 0.f), 15.f);
    return __fmul_rn(k, s);
}
__device__ __forceinline__ float qval_id(float y, float s) {
    float u = __fdiv_rn(y, s);
    float k = rintf(u);
    k = fminf(fmaxf(k, -8.f), 7.f);
    return __fmul_rn(k, s);
}

#define FMA4(acc, xv, wv)                        \
    do {                                         \
        acc = __fmaf_rn((xv).x, (wv).x, acc);    \
        acc = __fmaf_rn((xv).y, (wv).y, acc);    \
        acc = __fmaf_rn((xv).z, (wv).z, acc);    \
        acc = __fmaf_rn((xv).w, (wv).w, acc);    \
    } while (0)

// ---------------------------------------------------------------------------
// Weight quant (per-tensor symmetric, n=7) + transpose to [co][r][ci].
// ---------------------------------------------------------------------------
__global__ __launch_bounds__(256) void quant_weights_kernel(
    const float* w1, const float* w2, const float* w3, const float* w4,
    const float* w5, const float* wf1, const float* wf2) {
    __shared__ float red[256];
    __shared__ float s_scale;
    const float* src;
    float* dst;
    int n, ci_dim;
    switch (blockIdx.x) {
        case 0: src = w1;  dst = g_w1T;             n = 432;    ci_dim = 3;   break;
        case 1: src = w2;  dst = (float*)g_w2T4;    n = 4608;   ci_dim = 16;  break;
        case 2: src = w3;  dst = (float*)g_w3T4;    n = 18432;  ci_dim = 32;  break;
        case 3: src = w4;  dst = (float*)g_w4T4;    n = 73728;  ci_dim = 64;  break;
        case 4: src = w5;  dst = (float*)g_w5T4;    n = 294912; ci_dim = 128; break;
        case 5: src = wf1; dst = (float*)g_wf1q4;   n = 131072; ci_dim = 0;   break;
        default: src = wf2; dst = (float*)g_wf2q4;  n = 22016;  ci_dim = 0;   break;
    }
    int t = threadIdx.x;
    float m = 0.f;
    for (int i = t; i < n; i += 256) m = fmaxf(m, fabsf(src[i]));
    red[t] = m;
    __syncthreads();
    for (int s = 128; s > 0; s >>= 1) {
        if (t < s) red[t] = fmaxf(red[t], red[t + s]);
        __syncthreads();
    }
    if (t == 0) s_scale = __fdiv_rn(red[0], 7.0f);
    __syncthreads();
    float sc = s_scale;
    for (int i = t; i < n; i += 256) {
        float wq = 0.f;
        if (sc > 0.f) {
            float q = rintf(__fdiv_rn(src[i], sc));
            q = fminf(fmaxf(q, -7.f), 7.f);
            wq = __fmul_rn(q, sc);
        }
        if (ci_dim == 0) {
            dst[i] = wq;  // fc: [n][k] already k-contiguous
        } else {
            int co = i / (ci_dim * 9);
            int rem = i % (ci_dim * 9);
            int ci = rem / 9;
            int r = rem % 9;
            dst[(co * 9 + r) * ci_dim + ci] = wq;
        }
    }
}

// ---------------------------------------------------------------------------
// Monolithic network kernel: 8 images/block.
// ---------------------------------------------------------------------------
__global__ __launch_bounds__(256) void tsr_mono_kernel(
    const float* __restrict__ x,
    const float* __restrict__ b1c, const float* __restrict__ b2c,
    const float* __restrict__ b3c, const float* __restrict__ b4c,
    const float* __restrict__ b5c, const float* __restrict__ bf1c,
    const float* __restrict__ bf2c, const float* __restrict__ scl,
    float* __restrict__ out, int B) {
    __shared__ float4 sm4[2944];  // 11776 floats = 46KB
    float* sm = (float*)sm4;
    int t = threadIdx.x;
    int img0 = blockIdx.x * IMG_TILE;

    // ============ conv1: 3->16, 32x32 -> pooled 16x16 (NHWC out) ===========
    {
        float* sxT = sm;        // [32][32][3] = 3072
        float* sw1 = sm + 3072; // 432
        for (int i = t; i < 432; i += 256) sw1[i] = g_w1T[i];
        float s0 = scl[0];
        int py = t >> 4, px = t & 15;
        for (int im = 0; im < IMG_TILE; im++) {
            __syncthreads();
            const float* xs = x + (size_t)(img0 + im) * 3072;
            for (int i = t; i < 3072; i += 256) {
                int ci = i >> 10, sp = i & 1023;
                sxT[sp * 3 + ci] = xs[i];
            }
            __syncthreads();
            float win[4][4][3];
#pragma unroll
            for (int wy = 0; wy < 4; wy++) {
                int iy = 2 * py - 1 + wy;
#pragma unroll
                for (int wx = 0; wx < 4; wx++) {
                    int ix = 2 * px - 1 + wx;
                    bool v = (iy >= 0 && iy < 32 && ix >= 0 && ix < 32);
#pragma unroll
                    for (int ci = 0; ci < 3; ci++)
                        win[wy][wx][ci] = v ? sxT[(iy * 32 + ix) * 3 + ci] : 0.f;
                }
            }
            float* o = (float*)(g_a1 + (size_t)(img0 + im) * 1024);
            for (int co = 0; co < 16; co++) {
                float a0 = 0.f, a1 = 0.f, a2 = 0.f, a3 = 0.f;
#pragma unroll
                for (int r = 0; r < 9; r++) {
                    int ky = r / 3, kx = r % 3;
#pragma unroll
                    for (int ci = 0; ci < 3; ci++) {
                        float wv = sw1[co * 27 + r * 3 + ci];
                        a0 = __fmaf_rn(win[ky][kx][ci], wv, a0);
                        a1 = __fmaf_rn(win[ky][kx + 1][ci], wv, a1);
                        a2 = __fmaf_rn(win[ky + 1][kx][ci], wv, a2);
                        a3 = __fmaf_rn(win[ky + 1][kx + 1][ci], wv, a3);
                    }
                }
                float mx = fmaxf(fmaxf(a0, a1), fmaxf(a2, a3));
                float y = __fadd_rn(mx, __ldg(b1c + co));
                o[(py * 16 + px) * 16 + co] = qval_relu(y, s0);
            }
        }
    }
    __syncthreads();

    // ============ conv2: 16->32, 16x16 -> pooled 8x8 =======================
    {
        float4* sw = sm4;          // 32co*9*4 = 1152 f4
        float4* sx = sm4 + 1152;   // 1024 f4 (one image NHWC)
        for (int i = t; i < 1152; i += 256) sw[i] = g_w2T4[i];
        float s_out = scl[1];
        int sp = t >> 2, cp = t & 3;
        int py = sp >> 3, px = sp & 7;
        for (int im = 0; im < IMG_TILE; im++) {
            __syncthreads();
            const float4* src = g_a1 + (size_t)(img0 + im) * 1024;
            for (int i = t; i < 1024; i += 256) sx[i] = src[i];
            __syncthreads();
            float acc[8][4];
#pragma unroll
            for (int c = 0; c < 8; c++)
#pragma unroll
                for (int p = 0; p < 4; p++) acc[c][p] = 0.f;
#pragma unroll
            for (int r = 0; r < 9; r++) {
                int ky = r / 3, kx = r % 3;
                int o[4];
                bool v[4];
#pragma unroll
                for (int p = 0; p < 4; p++) {
                    int iy = 2 * py + (p >> 1) - 1 + ky;
                    int ix = 2 * px + (p & 1) - 1 + kx;
                    v[p] = ((unsigned)iy < 16u) && ((unsigned)ix < 16u);
                    o[p] = (iy * 16 + ix) * 4;
                }
#pragma unroll
                for (int ci4 = 0; ci4 < 4; ci4++) {
                    float4 xv[4];
#pragma unroll
                    for (int p = 0; p < 4; p++)
                        xv[p] = v[p] ? sx[o[p] + ci4] : make_float4(0.f, 0.f, 0.f, 0.f);
#pragma unroll
                    for (int c = 0; c < 8; c++) {
                        float4 wv = sw[((cp * 8 + c) * 9 + r) * 4 + ci4];
#pragma unroll
                        for (int p = 0; p < 4; p++) FMA4(acc[c][p], xv[p], wv);
                    }
                }
            }
            float* o2 = (float*)(g_a2 + (size_t)(img0 + im) * 512);
#pragma unroll
            for (int c = 0; c < 8; c++) {
                int co = cp * 8 + c;
                float mx = fmaxf(fmaxf(acc[c][0], acc[c][1]), fmaxf(acc[c][2], acc[c][3]));
                float y = __fadd_rn(mx, __ldg(b2c + co));
                o2[sp * 32 + co] = qval_relu(y, s_out);
            }
        }
    }
    __syncthreads();

    // ============ conv3: 32->64, 8x8 -> pooled 4x4 (2 co-stages) ===========
    {
        float4* sw = sm4;          // 32co*9*8 = 2304 f4
        float4* sx = sm4 + 2304;   // 512 f4
        float s_out = scl[2];
        int sp = t >> 4, cp = t & 15;
        int py = sp >> 2, px = sp & 3;
        for (int stg = 0; stg < 2; stg++) {
            __syncthreads();
            for (int i = t; i < 2304; i += 256) sw[i] = g_w3T4[stg * 2304 + i];
            for (int im = 0; im < IMG_TILE; im++) {
                __syncthreads();
                const float4* src = g_a2 + (size_t)(img0 + im) * 512;
                for (int i = t; i < 512; i += 256) sx[i] = src[i];
                __syncthreads();
                float acc[2][4];
#pragma unroll
                for (int c = 0; c < 2; c++)
#pragma unroll
                    for (int p = 0; p < 4; p++) acc[c][p] = 0.f;
#pragma unroll
                for (int r = 0; r < 9; r++) {
                    int ky = r / 3, kx = r % 3;
                    int o[4];
                    bool v[4];
#pragma unroll
                    for (int p = 0; p < 4; p++) {
                        int iy = 2 * py + (p >> 1) - 1 + ky;
                        int ix = 2 * px + (p & 1) - 1 + kx;
                        v[p] = ((unsigned)iy < 8u) && ((unsigned)ix < 8u);
                        o[p] = (iy * 8 + ix) * 8;
                    }
#pragma unroll
                    for (int ci4 = 0; ci4 < 8; ci4++) {
                        float4 xv[4];
#pragma unroll
                        for (int p = 0; p < 4; p++)
                            xv[p] = v[p] ? sx[o[p] + ci4] : make_float4(0.f, 0.f, 0.f, 0.f);
#pragma unroll
                        for (int c = 0; c < 2; c++) {
                            float4 wv = sw[((cp * 2 + c) * 9 + r) * 8 + ci4];
#pragma unroll
                            for (int p = 0; p < 4; p++) FMA4(acc[c][p], xv[p], wv);
                        }
                    }
                }
                float* o3 = (float*)(g_a3 + (size_t)(img0 + im) * 256);
#pragma unroll
                for (int c = 0; c < 2; c++) {
                    int co = stg * 32 + cp * 2 + c;
                    float mx = fmaxf(fmaxf(acc[c][0], acc[c][1]), fmaxf(acc[c][2], acc[c][3]));
                    float y = __fadd_rn(mx, __ldg(b3c + co));
                    o3[sp * 64 + co] = qval_relu(y, s_out);
                }
            }
        }
    }
    __syncthreads();

    // ============ conv4: 64->128, 4x4 -> pooled 2x2 (weights from global) ==
    {
        float4* sx = sm4;  // 8img * 256 f4 = 2048 f4
        const float4* src = g_a3 + (size_t)img0 * 256;
        for (int i = t; i < 2048; i += 256) sx[i] = src[i];
        __syncthreads();
        float s_out = scl[3];
        int co = t & 127, half = t >> 7;
        float b = __ldg(b4c + co);
        for (int j = 0; j < 4; j++) {
            int img = half * 4 + j;
            float acc[16];
#pragma unroll
            for (int p = 0; p < 16; p++) acc[p] = 0.f;
#pragma unroll
            for (int r = 0; r < 9; r++) {
                int ky = r / 3, kx = r % 3;
#pragma unroll
                for (int ci4 = 0; ci4 < 16; ci4++) {
                    float4 wv = __ldg(&g_w4T4[(co * 9 + r) * 16 + ci4]);
#pragma unroll
                    for (int oy = 0; oy < 4; oy++) {
                        int iy = oy - 1 + ky;
                        if (iy < 0 || iy > 3) continue;
#pragma unroll
                        for (int ox = 0; ox < 4; ox++) {
                            int ix = ox - 1 + kx;
                            if (ix < 0 || ix > 3) continue;
                            float4 xv = sx[(img * 16 + (iy * 4 + ix)) * 16 + ci4];
                            FMA4(acc[oy * 4 + ox], xv, wv);
                        }
                    }
                }
            }
            float* o4 = (float*)(g_a4 + (size_t)(img0 + img) * 128);
#pragma unroll
            for (int qy = 0; qy < 2; qy++)
#pragma unroll
                for (int qx = 0; qx < 2; qx++) {
                    float mx = fmaxf(
                        fmaxf(acc[(2 * qy) * 4 + 2 * qx], acc[(2 * qy) * 4 + 2 * qx + 1]),
                        fmaxf(acc[(2 * qy + 1) * 4 + 2 * qx], acc[(2 * qy + 1) * 4 + 2 * qx + 1]));
                    float y = __fadd_rn(mx, b);
                    o4[(qy * 2 + qx) * 128 + co] = qval_relu(y, s_out);
                }
        }
    }
    __syncthreads();

    // ============ conv5: 128->256, 2x2 -> pooled 1x1 (weights from global) =
    {
        float4* sx = sm4;             // 8img * 128 f4 = 1024 f4
        float* a5s = sm + 4096;       // 8 x 256 values
        const float4* src = g_a4 + (size_t)img0 * 128;
        for (int i = t; i < 1024; i += 256) sx[i] = src[i];
        __syncthreads();
        float s_out = scl[4];
        int co = t;
        float acc[8][4];
#pragma unroll
        for (int im = 0; im < 8; im++)
#pragma unroll
            for (int p = 0; p < 4; p++) acc[im][p] = 0.f;
#pragma unroll
        for (int r = 0; r < 9; r++) {
            int ky = r / 3, kx = r % 3;
#pragma unroll
            for (int ci4 = 0; ci4 < 32; ci4++) {
                float4 wv = __ldg(&g_w5T4[(co * 9 + r) * 32 + ci4]);
#pragma unroll
                for (int im = 0; im < 8; im++) {
#pragma unroll
                    for (int p = 0; p < 4; p++) {
                        int iy = (p >> 1) - 1 + ky;
                        int ix = (p & 1) - 1 + kx;
                        if (iy < 0 || iy > 1 || ix < 0 || ix > 1) continue;
                        float4 xv = sx[(im * 4 + (iy * 2 + ix)) * 32 + ci4];
                        FMA4(acc[im][p], xv, wv);
                    }
                }
            }
        }
        float b = __ldg(b5c + co);
#pragma unroll
        for (int im = 0; im < 8; im++) {
            float mx = fmaxf(fmaxf(acc[im][0], acc[im][1]), fmaxf(acc[im][2], acc[im][3]));
            float y = __fadd_rn(mx, b);
            a5s[im * 256 + co] = qval_relu(y, s_out);
        }
    }
    __syncthreads();

    // ============ fc1: 256->512 (k ascending) ==============================
    {
        const float4* a5s4 = (const float4*)(sm + 4096);  // [8][64]
        float* f1s = sm + 6400;                            // 8 x 512
        float s_out = scl[5];
#pragma unroll
        for (int rep = 0; rep < 2; rep++) {
            int n = t + rep * 256;
            float acc[8];
#pragma unroll
            for (int im = 0; im < 8; im++) acc[im] = 0.f;
            for (int k4 = 0; k4 < 64; k4++) {
                float4 wv = __ldg(&g_wf1q4[n * 64 + k4]);
#pragma unroll
                for (int im = 0; im < 8; im++) {
                    float4 xv = a5s4[im * 64 + k4];
                    FMA4(acc[im], xv, wv);
                }
            }
            float b = __ldg(bf1c + n);
#pragma unroll
            for (int im = 0; im < 8; im++) {
                float y = __fadd_rn(acc[im], b);
                f1s[im * 512 + n] = qval_relu(y, s_out);
            }
        }
    }
    __syncthreads();

    // ============ fc2: 512->43 (k ascending) + quant_identity ==============
    {
        const float4* f1s4 = (const float4*)(sm + 6400);  // [8][128]
        float* lg = sm;                                    // 8 x 43 values
        float s_out = scl[6];
        if (t < 172) {
            int n = t >> 2, pair = t & 3;
            float a0 = 0.f, a1 = 0.f;
            for (int k4 = 0; k4 < 128; k4++) {
                float4 wv = __ldg(&g_wf2q4[n * 128 + k4]);
                float4 x0 = f1s4[(pair * 2) * 128 + k4];
                float4 x1 = f1s4[(pair * 2 + 1) * 128 + k4];
                FMA4(a0, x0, wv);
                FMA4(a1, x1, wv);
            }
            float b = __ldg(bf2c + n);
            lg[(pair * 2) * 43 + n] = qval_id(__fadd_rn(a0, b), s_out);
            lg[(pair * 2 + 1) * 43 + n] = qval_id(__fadd_rn(a1, b), s_out);
        }
    }
    __syncthreads();

    // ============ softmax (43 classes, one warp per image) =================
    {
        const float* lg = sm;
        int lane = t & 31, w = t >> 5;
        float v0 = lg[w * 43 + lane];
        float v1 = (lane < 11) ? lg[w * 43 + 32 + lane] : -INFINITY;
        float mx = fmaxf(v0, v1);
#pragma unroll
        for (int o = 16; o > 0; o >>= 1) mx = fmaxf(mx, __shfl_xor_sync(0xffffffffu, mx, o));
        float e0 = expf(v0 - mx);
        float e1 = (lane < 11) ? expf(v1 - mx) : 0.f;
        float sum = e0 + e1;
#pragma unroll
        for (int o = 16; o > 0; o >>= 1) sum += __shfl_xor_sync(0xffffffffu, sum, o);
        if ((img0 + w) < B) {
            out[(size_t)(img0 + w) * 43 + lane] = __fdiv_rn(e0, sum);
            if (lane < 11)
                out[(size_t)(img0 + w) * 43 + 32 + lane] = __fdiv_rn(e1, sum);
        }
    }
}

// ---------------------------------------------------------------------------
extern "C" void kernel_launch(void* const* d_in, const int* in_sizes, int n_in,
                              void* d_out, int out_size) {
    const float *x = 0, *w1 = 0, *b1 = 0, *w2 = 0, *b2 = 0, *w3 = 0, *b3 = 0;
    const float *w4 = 0, *b4 = 0, *w5 = 0, *b5 = 0, *wf1 = 0, *bf1 = 0;
    const float *wf2 = 0, *bf2 = 0, *scl = 0;
    int B = 2048;
    for (int i = 0; i < n_in; i++) {
        const float* p = (const float*)d_in[i];
        switch (in_sizes[i]) {
            case 432:    w1 = p;  break;
            case 16:     b1 = p;  break;
            case 4608:   w2 = p;  break;
            case 32:     b2 = p;  break;
            case 18432:  w3 = p;  break;
            case 64:     b3 = p;  break;
            case 73728:  w4 = p;  break;
            case 128:    b4 = p;  break;
            case 294912: w5 = p;  break;
            case 256:    b5 = p;  break;
            case 131072: wf1 = p; break;
            case 512:    bf1 = p; break;
            case 22016:  wf2 = p; break;
            case 43:     bf2 = p; break;
            case 7:      scl = p; break;
            default:     x = p; B = in_sizes[i] / 3072; break;
        }
    }
    float* out = (float*)d_out;

    quant_weights_kernel<<<7, 256>>>(w1, w2, w3, w4, w5, wf1, wf2);
    int nblk = (B + IMG_TILE - 1) / IMG_TILE;
    tsr_mono_kernel<<<nblk, 256>>>(x, b1, b2, b3, b4, b5, bf1, bf2, scl, out, B);
}

// round 10
// speedup vs baseline: 1.5512x; 1.5512x over previous
#include <cuda_runtime.h>
#include <math.h>
#include <stdint.h>

// ---------------------------------------------------------------------------
// TSRNet 4-bit fake-quant CNN — per-layer kernels, reference-order fp32 FMA.
// Reduction chains byte-identical to the passing R8 kernel: convs r-major /
// ci-fastest, dots k-ascending, one fp32 accumulator per output.
// R10: bounded unrolling (unroll 2 on big ci4 loops) so no kernel spills to
// local memory (the R9 lmem-pool growth tripped the harness memcheck).
// ---------------------------------------------------------------------------

#define BMAX 2048

// transposed quantized weights, float4-aligned
__device__ float  g_w1T[16 * 27];            // [co][r][ci], ci=3
__device__ float4 g_w2T4[32 * 9 * 4];        // [co][r][ci4], CI=16
__device__ float4 g_w3T4[64 * 9 * 8];        // CI=32
__device__ float4 g_w4T4[128 * 9 * 16];      // CI=64
__device__ float4 g_w5T4[256 * 9 * 32];      // CI=128
__device__ float4 g_wf1q4[512 * 64];         // [n][k4], K=256
__device__ float4 g_wf2q4[43 * 128];         // K=512

// NHWC activations (values)
__device__ float4 g_a1[BMAX * 1024];  // [img][256 sp][16ci]/4
__device__ float4 g_a2[BMAX * 512];   // [img][64][32]/4
__device__ float4 g_a3[BMAX * 256];   // [img][16][64]/4
__device__ float4 g_a4[BMAX * 128];   // [img][4][128]/4
__device__ float  g_a5[BMAX * 256];   // [img][256]

__device__ __forceinline__ float qval_relu(float y, float s) {
    float u = __fdiv_rn(y, s);
    float k = rintf(u);
    k = fminf(fmaxf(k, 0.f), 15.f);
    return __fmul_rn(k, s);
}
__device__ __forceinline__ float qval_id(float y, float s) {
    float u = __fdiv_rn(y, s);
    float k = rintf(u);
    k = fminf(fmaxf(k, -8.f), 7.f);
    return __fmul_rn(k, s);
}

#define FMA4(acc, xv, wv)                        \
    do {                                         \
        acc = __fmaf_rn((xv).x, (wv).x, acc);    \
        acc = __fmaf_rn((xv).y, (wv).y, acc);    \
        acc = __fmaf_rn((xv).z, (wv).z, acc);    \
        acc = __fmaf_rn((xv).w, (wv).w, acc);    \
    } while (0)

// ---------------------------------------------------------------------------
// Weight quant (per-tensor symmetric, n=7) + transpose to [co][r][ci].
// ---------------------------------------------------------------------------
__global__ __launch_bounds__(256) void quant_weights_kernel(
    const float* w1, const float* w2, const float* w3, const float* w4,
    const float* w5, const float* wf1, const float* wf2) {
    __shared__ float red[256];
    __shared__ float s_scale;
    const float* src;
    float* dst;
    int n, ci_dim;
    switch (blockIdx.x) {
        case 0: src = w1;  dst = g_w1T;            n = 432;    ci_dim = 3;   break;
        case 1: src = w2;  dst = (float*)g_w2T4;   n = 4608;   ci_dim = 16;  break;
        case 2: src = w3;  dst = (float*)g_w3T4;   n = 18432;  ci_dim = 32;  break;
        case 3: src = w4;  dst = (float*)g_w4T4;   n = 73728;  ci_dim = 64;  break;
        case 4: src = w5;  dst = (float*)g_w5T4;   n = 294912; ci_dim = 128; break;
        case 5: src = wf1; dst = (float*)g_wf1q4;  n = 131072; ci_dim = 0;   break;
        default: src = wf2; dst = (float*)g_wf2q4; n = 22016;  ci_dim = 0;   break;
    }
    int t = threadIdx.x;
    float m = 0.f;
    for (int i = t; i < n; i += 256) m = fmaxf(m, fabsf(src[i]));
    red[t] = m;
    __syncthreads();
    for (int s = 128; s > 0; s >>= 1) {
        if (t < s) red[t] = fmaxf(red[t], red[t + s]);
        __syncthreads();
    }
    if (t == 0) s_scale = __fdiv_rn(red[0], 7.0f);
    __syncthreads();
    float sc = s_scale;
    for (int i = t; i < n; i += 256) {
        float wq = 0.f;
        if (sc > 0.f) {
            float q = rintf(__fdiv_rn(src[i], sc));
            q = fminf(fmaxf(q, -7.f), 7.f);
            wq = __fmul_rn(q, sc);
        }
        if (ci_dim == 0) {
            dst[i] = wq;
        } else {
            int co = i / (ci_dim * 9);
            int rem = i % (ci_dim * 9);
            int ci = rem / 9;
            int r = rem % 9;
            dst[(co * 9 + r) * ci_dim + ci] = wq;
        }
    }
}

// ---------------------------------------------------------------------------
// conv1: 3->16, 32x32 -> pooled 16x16. One image per block.
// ---------------------------------------------------------------------------
__global__ __launch_bounds__(256) void conv1_kernel(
    const float* __restrict__ x, const float* __restrict__ b1c,
    const float* __restrict__ scl) {
    __shared__ float sxT[3072];  // [32][32][3]
    __shared__ float sw1[432];
    int t = threadIdx.x;
    int img = blockIdx.x;
    for (int i = t; i < 432; i += 256) sw1[i] = g_w1T[i];
    const float* xs = x + (size_t)img * 3072;
    for (int i = t; i < 3072; i += 256) {
        int ci = i >> 10, sp = i & 1023;
        sxT[sp * 3 + ci] = xs[i];
    }
    __syncthreads();
    float s0 = scl[0];
    int py = t >> 4, px = t & 15;
    float win[4][4][3];
#pragma unroll
    for (int wy = 0; wy < 4; wy++) {
        int iy = 2 * py - 1 + wy;
#pragma unroll
        for (int wx = 0; wx < 4; wx++) {
            int ix = 2 * px - 1 + wx;
            bool v = (iy >= 0 && iy < 32 && ix >= 0 && ix < 32);
#pragma unroll
            for (int ci = 0; ci < 3; ci++)
                win[wy][wx][ci] = v ? sxT[(iy * 32 + ix) * 3 + ci] : 0.f;
        }
    }
    float* o = (float*)(g_a1 + (size_t)img * 1024);
#pragma unroll 2
    for (int co = 0; co < 16; co++) {
        float a0 = 0.f, a1 = 0.f, a2 = 0.f, a3 = 0.f;
#pragma unroll
        for (int r = 0; r < 9; r++) {
            int ky = r / 3, kx = r % 3;
#pragma unroll
            for (int ci = 0; ci < 3; ci++) {
                float wv = sw1[co * 27 + r * 3 + ci];
                a0 = __fmaf_rn(win[ky][kx][ci], wv, a0);
                a1 = __fmaf_rn(win[ky][kx + 1][ci], wv, a1);
                a2 = __fmaf_rn(win[ky + 1][kx][ci], wv, a2);
                a3 = __fmaf_rn(win[ky + 1][kx + 1][ci], wv, a3);
            }
        }
        float mx = fmaxf(fmaxf(a0, a1), fmaxf(a2, a3));
        float y = __fadd_rn(mx, __ldg(b1c + co));
        o[(py * 16 + px) * 16 + co] = qval_relu(y, s0);
    }
}

// ---------------------------------------------------------------------------
// conv2: 16->32, 16x16 -> pooled 8x8. One image per block.
// ---------------------------------------------------------------------------
__global__ __launch_bounds__(256) void conv2_kernel(
    const float* __restrict__ b2c, const float* __restrict__ scl) {
    __shared__ float4 sw[1152];  // 32co*9*4
    __shared__ float4 sx[1024];  // one image NHWC
    int t = threadIdx.x;
    int img = blockIdx.x;
    for (int i = t; i < 1152; i += 256) sw[i] = g_w2T4[i];
    const float4* src = g_a1 + (size_t)img * 1024;
    for (int i = t; i < 1024; i += 256) sx[i] = src[i];
    __syncthreads();
    float s_out = scl[1];
    int sp = t >> 2, cp = t & 3;
    int py = sp >> 3, px = sp & 7;
    float acc[8][4];
#pragma unroll
    for (int c = 0; c < 8; c++)
#pragma unroll
        for (int p = 0; p < 4; p++) acc[c][p] = 0.f;
#pragma unroll
    for (int r = 0; r < 9; r++) {
        int ky = r / 3, kx = r % 3;
        int o[4];
        bool v[4];
#pragma unroll
        for (int p = 0; p < 4; p++) {
            int iy = 2 * py + (p >> 1) - 1 + ky;
            int ix = 2 * px + (p & 1) - 1 + kx;
            v[p] = ((unsigned)iy < 16u) && ((unsigned)ix < 16u);
            o[p] = (iy * 16 + ix) * 4;
        }
#pragma unroll 2
        for (int ci4 = 0; ci4 < 4; ci4++) {
            float4 xv[4];
#pragma unroll
            for (int p = 0; p < 4; p++)
                xv[p] = v[p] ? sx[o[p] + ci4] : make_float4(0.f, 0.f, 0.f, 0.f);
#pragma unroll
            for (int c = 0; c < 8; c++) {
                float4 wv = sw[((cp * 8 + c) * 9 + r) * 4 + ci4];
#pragma unroll
                for (int p = 0; p < 4; p++) FMA4(acc[c][p], xv[p], wv);
            }
        }
    }
    float* o2 = (float*)(g_a2 + (size_t)img * 512);
#pragma unroll
    for (int c = 0; c < 8; c++) {
        int co = cp * 8 + c;
        float mx = fmaxf(fmaxf(acc[c][0], acc[c][1]), fmaxf(acc[c][2], acc[c][3]));
        float y = __fadd_rn(mx, __ldg(b2c + co));
        o2[sp * 32 + co] = qval_relu(y, s_out);
    }
}

// ---------------------------------------------------------------------------
// conv3: 32->64, 8x8 -> pooled 4x4. Grid (img, co-half). 45KB static SMEM.
// ---------------------------------------------------------------------------
__global__ __launch_bounds__(256) void conv3_kernel(
    const float* __restrict__ b3c, const float* __restrict__ scl) {
    __shared__ float4 sw[2304];  // 32co*9*8
    __shared__ float4 sx[512];
    int t = threadIdx.x;
    int img = blockIdx.x;
    int stg = blockIdx.y;
    for (int i = t; i < 2304; i += 256) sw[i] = g_w3T4[stg * 2304 + i];
    const float4* src = g_a2 + (size_t)img * 512;
    for (int i = t; i < 512; i += 256) sx[i] = src[i];
    __syncthreads();
    float s_out = scl[2];
    int sp = t >> 4, cp = t & 15;
    int py = sp >> 2, px = sp & 3;
    float acc[2][4];
#pragma unroll
    for (int c = 0; c < 2; c++)
#pragma unroll
        for (int p = 0; p < 4; p++) acc[c][p] = 0.f;
#pragma unroll
    for (int r = 0; r < 9; r++) {
        int ky = r / 3, kx = r % 3;
        int o[4];
        bool v[4];
#pragma unroll
        for (int p = 0; p < 4; p++) {
            int iy = 2 * py + (p >> 1) - 1 + ky;
            int ix = 2 * px + (p & 1) - 1 + kx;
            v[p] = ((unsigned)iy < 8u) && ((unsigned)ix < 8u);
            o[p] = (iy * 8 + ix) * 8;
        }
#pragma unroll 2
        for (int ci4 = 0; ci4 < 8; ci4++) {
            float4 xv[4];
#pragma unroll
            for (int p = 0; p < 4; p++)
                xv[p] = v[p] ? sx[o[p] + ci4] : make_float4(0.f, 0.f, 0.f, 0.f);
#pragma unroll
            for (int c = 0; c < 2; c++) {
                float4 wv = sw[((cp * 2 + c) * 9 + r) * 8 + ci4];
#pragma unroll
                for (int p = 0; p < 4; p++) FMA4(acc[c][p], xv[p], wv);
            }
        }
    }
    float* o3 = (float*)(g_a3 + (size_t)img * 256);
#pragma unroll
    for (int c = 0; c < 2; c++) {
        int co = stg * 32 + cp * 2 + c;
        float mx = fmaxf(fmaxf(acc[c][0], acc[c][1]), fmaxf(acc[c][2], acc[c][3]));
        float y = __fadd_rn(mx, __ldg(b3c + co));
        o3[sp * 64 + co] = qval_relu(y, s_out);
    }
}

// ---------------------------------------------------------------------------
// conv4: 64->128, 4x4 -> pooled 2x2. Two images per block. Weights via __ldg.
// Bounded unroll on ci4 (runtime loop) to avoid spills.
// ---------------------------------------------------------------------------
__global__ __launch_bounds__(256) void conv4_kernel(
    const float* __restrict__ b4c, const float* __restrict__ scl) {
    __shared__ float4 sx[512];  // 2 img x 256 f4
    int t = threadIdx.x;
    int img0 = blockIdx.x * 2;
    const float4* src = g_a3 + (size_t)img0 * 256;
    for (int i = t; i < 512; i += 256) sx[i] = src[i];
    __syncthreads();
    float s_out = scl[3];
    int co = t & 127, half = t >> 7;
    float b = __ldg(b4c + co);
    float acc[16];
#pragma unroll
    for (int p = 0; p < 16; p++) acc[p] = 0.f;
#pragma unroll
    for (int r = 0; r < 9; r++) {
        int ky = r / 3, kx = r % 3;
#pragma unroll 2
        for (int ci4 = 0; ci4 < 16; ci4++) {
            float4 wv = __ldg(&g_w4T4[(co * 9 + r) * 16 + ci4]);
#pragma unroll
            for (int oy = 0; oy < 4; oy++) {
                int iy = oy - 1 + ky;
                if (iy < 0 || iy > 3) continue;
#pragma unroll
                for (int ox = 0; ox < 4; ox++) {
                    int ix = ox - 1 + kx;
                    if (ix < 0 || ix > 3) continue;
                    float4 xv = sx[(half * 16 + (iy * 4 + ix)) * 16 + ci4];
                    FMA4(acc[oy * 4 + ox], xv, wv);
                }
            }
        }
    }
    float* o4 = (float*)(g_a4 + (size_t)(img0 + half) * 128);
#pragma unroll
    for (int qy = 0; qy < 2; qy++)
#pragma unroll
        for (int qx = 0; qx < 2; qx++) {
            float mx = fmaxf(
                fmaxf(acc[(2 * qy) * 4 + 2 * qx], acc[(2 * qy) * 4 + 2 * qx + 1]),
                fmaxf(acc[(2 * qy + 1) * 4 + 2 * qx], acc[(2 * qy + 1) * 4 + 2 * qx + 1]));
            float y = __fadd_rn(mx, b);
            o4[(qy * 2 + qx) * 128 + co] = qval_relu(y, s_out);
        }
}

// ---------------------------------------------------------------------------
// conv5: 128->256, 2x2 -> pooled 1x1. 8 images per block (weight reuse).
// Bounded unroll on ci4 (runtime loop) to avoid spills.
// ---------------------------------------------------------------------------
__global__ __launch_bounds__(256) void conv5_kernel(
    const float* __restrict__ b5c, const float* __restrict__ scl) {
    __shared__ float4 sx[1024];  // 8 img x 128 f4
    int t = threadIdx.x;
    int img0 = blockIdx.x * 8;
    const float4* src = g_a4 + (size_t)img0 * 128;
    for (int i = t; i < 1024; i += 256) sx[i] = src[i];
    __syncthreads();
    float s_out = scl[4];
    int co = t;
    float acc[8][4];
#pragma unroll
    for (int im = 0; im < 8; im++)
#pragma unroll
        for (int p = 0; p < 4; p++) acc[im][p] = 0.f;
#pragma unroll
    for (int r = 0; r < 9; r++) {
        int ky = r / 3, kx = r % 3;
#pragma unroll 2
        for (int ci4 = 0; ci4 < 32; ci4++) {
            float4 wv = __ldg(&g_w5T4[(co * 9 + r) * 32 + ci4]);
#pragma unroll
            for (int im = 0; im < 8; im++) {
#pragma unroll
                for (int p = 0; p < 4; p++) {
                    int iy = (p >> 1) - 1 + ky;
                    int ix = (p & 1) - 1 + kx;
                    if (iy < 0 || iy > 1 || ix < 0 || ix > 1) continue;
                    float4 xv = sx[(im * 4 + (iy * 2 + ix)) * 32 + ci4];
                    FMA4(acc[im][p], xv, wv);
                }
            }
        }
    }
    float b = __ldg(b5c + co);
#pragma unroll
    for (int im = 0; im < 8; im++) {
        float mx = fmaxf(fmaxf(acc[im][0], acc[im][1]), fmaxf(acc[im][2], acc[im][3]));
        float y = __fadd_rn(mx, b);
        g_a5[(size_t)(img0 + im) * 256 + co] = qval_relu(y, s_out);
    }
}

// ---------------------------------------------------------------------------
// head: fc1 (256->512 qrelu) + fc2 (512->43 qid) + softmax. 8 imgs/block.
// ---------------------------------------------------------------------------
__global__ __launch_bounds__(256) void head_kernel(
    const float* __restrict__ bf1c, const float* __restrict__ bf2c,
    const float* __restrict__ scl, float* __restrict__ out, int B) {
    __shared__ float smh[2048 + 4096 + 344];
    float* a5s = smh;          // 8 x 256
    float* f1s = smh + 2048;   // 8 x 512
    float* lg = smh + 6144;    // 8 x 43
    int t = threadIdx.x;
    int img0 = blockIdx.x * 8;
    const float* src = g_a5 + (size_t)img0 * 256;
    for (int i = t; i < 2048; i += 256) a5s[i] = src[i];
    __syncthreads();

    // fc1 (k ascending)
    {
        const float4* a5s4 = (const float4*)a5s;  // [8][64]
        float s_out = scl[5];
#pragma unroll
        for (int rep = 0; rep < 2; rep++) {
            int n = t + rep * 256;
            float acc[8];
#pragma unroll
            for (int im = 0; im < 8; im++) acc[im] = 0.f;
#pragma unroll 4
            for (int k4 = 0; k4 < 64; k4++) {
                float4 wv = __ldg(&g_wf1q4[n * 64 + k4]);
#pragma unroll
                for (int im = 0; im < 8; im++) {
                    float4 xv = a5s4[im * 64 + k4];
                    FMA4(acc[im], xv, wv);
                }
            }
            float b = __ldg(bf1c + n);
#pragma unroll
            for (int im = 0; im < 8; im++) {
                float y = __fadd_rn(acc[im], b);
                f1s[im * 512 + n] = qval_relu(y, s_out);
            }
        }
    }
    __syncthreads();

    // fc2 + quant_identity
    {
        const float4* f1s4 = (const float4*)f1s;  // [8][128]
        float s_out = scl[6];
        if (t < 172) {
            int n = t >> 2, pair = t & 3;
            float a0 = 0.f, a1 = 0.f;
#pragma unroll 4
            for (int k4 = 0; k4 < 128; k4++) {
                float4 wv = __ldg(&g_wf2q4[n * 128 + k4]);
                float4 x0 = f1s4[(pair * 2) * 128 + k4];
                float4 x1 = f1s4[(pair * 2 + 1) * 128 + k4];
                FMA4(a0, x0, wv);
                FMA4(a1, x1, wv);
            }
            float b = __ldg(bf2c + n);
            lg[(pair * 2) * 43 + n] = qval_id(__fadd_rn(a0, b), s_out);
            lg[(pair * 2 + 1) * 43 + n] = qval_id(__fadd_rn(a1, b), s_out);
        }
    }
    __syncthreads();

    // softmax (43 classes, one warp per image)
    {
        int lane = t & 31, w = t >> 5;
        float v0 = lg[w * 43 + lane];
        float v1 = (lane < 11) ? lg[w * 43 + 32 + lane] : -INFINITY;
        float mx = fmaxf(v0, v1);
#pragma unroll
        for (int o = 16; o > 0; o >>= 1) mx = fmaxf(mx, __shfl_xor_sync(0xffffffffu, mx, o));
        float e0 = expf(v0 - mx);
        float e1 = (lane < 11) ? expf(v1 - mx) : 0.f;
        float sum = e0 + e1;
#pragma unroll
        for (int o = 16; o > 0; o >>= 1) sum += __shfl_xor_sync(0xffffffffu, sum, o);
        if ((img0 + w) < B) {
            out[(size_t)(img0 + w) * 43 + lane] = __fdiv_rn(e0, sum);
            if (lane < 11)
                out[(size_t)(img0 + w) * 43 + 32 + lane] = __fdiv_rn(e1, sum);
        }
    }
}

// ---------------------------------------------------------------------------
extern "C" void kernel_launch(void* const* d_in, const int* in_sizes, int n_in,
                              void* d_out, int out_size) {
    const float *x = 0, *w1 = 0, *b1 = 0, *w2 = 0, *b2 = 0, *w3 = 0, *b3 = 0;
    const float *w4 = 0, *b4 = 0, *w5 = 0, *b5 = 0, *wf1 = 0, *bf1 = 0;
    const float *wf2 = 0, *bf2 = 0, *scl = 0;
    int B = 2048;
    for (int i = 0; i < n_in; i++) {
        const float* p = (const float*)d_in[i];
        switch (in_sizes[i]) {
            case 432:    w1 = p;  break;
            case 16:     b1 = p;  break;
            case 4608:   w2 = p;  break;
            case 32:     b2 = p;  break;
            case 18432:  w3 = p;  break;
            case 64:     b3 = p;  break;
            case 73728:  w4 = p;  break;
            case 128:    b4 = p;  break;
            case 294912: w5 = p;  break;
            case 256:    b5 = p;  break;
            case 131072: wf1 = p; break;
            case 512:    bf1 = p; break;
            case 22016:  wf2 = p; break;
            case 43:     bf2 = p; break;
            case 7:      scl = p; break;
            default:     x = p; B = in_sizes[i] / 3072; break;
        }
    }
    float* out = (float*)d_out;

    quant_weights_kernel<<<7, 256>>>(w1, w2, w3, w4, w5, wf1, wf2);
    conv1_kernel<<<B, 256>>>(x, b1, scl);
    conv2_kernel<<<B, 256>>>(b2, scl);
    conv3_kernel<<<dim3(B, 2), 256>>>(b3, scl);
    conv4_kernel<<<B / 2, 256>>>(b4, scl);
    conv5_kernel<<<B / 8, 256>>>(b5, scl);
    head_kernel<<<B / 8, 256>>>(bf1, bf2, scl, out, B);
}

// round 11
// speedup vs baseline: 1.7593x; 1.1341x over previous
#include <cuda_runtime.h>
#include <math.h>
#include <stdint.h>

// ---------------------------------------------------------------------------
// TSRNet 4-bit fake-quant CNN — per-layer kernels, reference-order fp32 FMA.
// R11: conv2/3/4 remapped so co is warp-uniform (weights broadcast via __ldg)
// and lanes span (image x pooled pixel); each activation LDS feeds 8co x 4pos
// FMAs. Reduction chains byte-identical to R8 (r-major, ci-ascending).
// ---------------------------------------------------------------------------

#define BMAX 2048

__device__ float  g_w1T[16 * 27];            // [co][r][ci], ci=3
__device__ float4 g_w2T4[32 * 9 * 4];        // [co][r][ci4], CI=16
__device__ float4 g_w3T4[64 * 9 * 8];        // CI=32
__device__ float4 g_w4T4[128 * 9 * 16];      // CI=64
__device__ float4 g_w5T4[256 * 9 * 32];      // CI=128
__device__ float4 g_wf1q4[512 * 64];         // [n][k4], K=256
__device__ float4 g_wf2q4[43 * 128];         // K=512

__device__ float4 g_a1[BMAX * 1024];  // [img][256 sp][16ci]/4
__device__ float4 g_a2[BMAX * 512];   // [img][64][32]/4
__device__ float4 g_a3[BMAX * 256];   // [img][16][64]/4
__device__ float4 g_a4[BMAX * 128];   // [img][4][128]/4
__device__ float  g_a5[BMAX * 256];   // [img][256]

__device__ __forceinline__ float qval_relu(float y, float s) {
    float u = __fdiv_rn(y, s);
    float k = rintf(u);
    k = fminf(fmaxf(k, 0.f), 15.f);
    return __fmul_rn(k, s);
}
__device__ __forceinline__ float qval_id(float y, float s) {
    float u = __fdiv_rn(y, s);
    float k = rintf(u);
    k = fminf(fmaxf(k, -8.f), 7.f);
    return __fmul_rn(k, s);
}

#define FMA4(acc, xv, wv)                        \
    do {                                         \
        acc = __fmaf_rn((xv).x, (wv).x, acc);    \
        acc = __fmaf_rn((xv).y, (wv).y, acc);    \
        acc = __fmaf_rn((xv).z, (wv).z, acc);    \
        acc = __fmaf_rn((xv).w, (wv).w, acc);    \
    } while (0)

// ---------------------------------------------------------------------------
// Weight quant (per-tensor symmetric, n=7) + transpose to [co][r][ci].
// ---------------------------------------------------------------------------
__global__ __launch_bounds__(256) void quant_weights_kernel(
    const float* w1, const float* w2, const float* w3, const float* w4,
    const float* w5, const float* wf1, const float* wf2) {
    __shared__ float red[256];
    __shared__ float s_scale;
    const float* src;
    float* dst;
    int n, ci_dim;
    switch (blockIdx.x) {
        case 0: src = w1;  dst = g_w1T;            n = 432;    ci_dim = 3;   break;
        case 1: src = w2;  dst = (float*)g_w2T4;   n = 4608;   ci_dim = 16;  break;
        case 2: src = w3;  dst = (float*)g_w3T4;   n = 18432;  ci_dim = 32;  break;
        case 3: src = w4;  dst = (float*)g_w4T4;   n = 73728;  ci_dim = 64;  break;
        case 4: src = w5;  dst = (float*)g_w5T4;   n = 294912; ci_dim = 128; break;
        case 5: src = wf1; dst = (float*)g_wf1q4;  n = 131072; ci_dim = 0;   break;
        default: src = wf2; dst = (float*)g_wf2q4; n = 22016;  ci_dim = 0;   break;
    }
    int t = threadIdx.x;
    float m = 0.f;
    for (int i = t; i < n; i += 256) m = fmaxf(m, fabsf(src[i]));
    red[t] = m;
    __syncthreads();
    for (int s = 128; s > 0; s >>= 1) {
        if (t < s) red[t] = fmaxf(red[t], red[t + s]);
        __syncthreads();
    }
    if (t == 0) s_scale = __fdiv_rn(red[0], 7.0f);
    __syncthreads();
    float sc = s_scale;
    for (int i = t; i < n; i += 256) {
        float wq = 0.f;
        if (sc > 0.f) {
            float q = rintf(__fdiv_rn(src[i], sc));
            q = fminf(fmaxf(q, -7.f), 7.f);
            wq = __fmul_rn(q, sc);
        }
        if (ci_dim == 0) {
            dst[i] = wq;
        } else {
            int co = i / (ci_dim * 9);
            int rem = i % (ci_dim * 9);
            int ci = rem / 9;
            int r = rem % 9;
            dst[(co * 9 + r) * ci_dim + ci] = wq;
        }
    }
}

// ---------------------------------------------------------------------------
// conv1: 3->16, 32x32 -> pooled 16x16. One image per block (register conv).
// ---------------------------------------------------------------------------
__global__ __launch_bounds__(256) void conv1_kernel(
    const float* __restrict__ x, const float* __restrict__ b1c,
    const float* __restrict__ scl) {
    __shared__ float sxT[3072];  // [32][32][3]
    __shared__ float sw1[432];
    int t = threadIdx.x;
    int img = blockIdx.x;
    for (int i = t; i < 432; i += 256) sw1[i] = g_w1T[i];
    const float* xs = x + (size_t)img * 3072;
    for (int i = t; i < 3072; i += 256) {
        int ci = i >> 10, sp = i & 1023;
        sxT[sp * 3 + ci] = xs[i];
    }
    __syncthreads();
    float s0 = scl[0];
    int py = t >> 4, px = t & 15;
    float win[4][4][3];
#pragma unroll
    for (int wy = 0; wy < 4; wy++) {
        int iy = 2 * py - 1 + wy;
#pragma unroll
        for (int wx = 0; wx < 4; wx++) {
            int ix = 2 * px - 1 + wx;
            bool v = (iy >= 0 && iy < 32 && ix >= 0 && ix < 32);
#pragma unroll
            for (int ci = 0; ci < 3; ci++)
                win[wy][wx][ci] = v ? sxT[(iy * 32 + ix) * 3 + ci] : 0.f;
        }
    }
    float* o = (float*)(g_a1 + (size_t)img * 1024);
#pragma unroll 2
    for (int co = 0; co < 16; co++) {
        float a0 = 0.f, a1 = 0.f, a2 = 0.f, a3 = 0.f;
#pragma unroll
        for (int r = 0; r < 9; r++) {
            int ky = r / 3, kx = r % 3;
#pragma unroll
            for (int ci = 0; ci < 3; ci++) {
                float wv = sw1[co * 27 + r * 3 + ci];
                a0 = __fmaf_rn(win[ky][kx][ci], wv, a0);
                a1 = __fmaf_rn(win[ky][kx + 1][ci], wv, a1);
                a2 = __fmaf_rn(win[ky + 1][kx][ci], wv, a2);
                a3 = __fmaf_rn(win[ky + 1][kx + 1][ci], wv, a3);
            }
        }
        float mx = fmaxf(fmaxf(a0, a1), fmaxf(a2, a3));
        float y = __fadd_rn(mx, __ldg(b1c + co));
        o[(py * 16 + px) * 16 + co] = qval_relu(y, s0);
    }
}

// ---------------------------------------------------------------------------
// conv2: 16->32, 16x16 -> pooled 8x8. One image/block; warp = (co-group of 8,
// sp-half); lanes = 32 pooled sp. Weights warp-uniform via __ldg.
// ---------------------------------------------------------------------------
__global__ __launch_bounds__(256) void conv2_kernel(
    const float* __restrict__ b2c, const float* __restrict__ scl) {
    __shared__ float4 sx[1024];  // one image NHWC 16x16x16
    int t = threadIdx.x;
    int img = blockIdx.x;
    const float4* src = g_a1 + (size_t)img * 1024;
    for (int i = t; i < 1024; i += 256) sx[i] = src[i];
    __syncthreads();
    float s_out = scl[1];
    int warp = t >> 5, lane = t & 31;
    int h = warp & 1, cg = warp >> 1;   // sp-half, co-group
    int co0 = cg * 8;
    int sp = h * 32 + lane;
    int py = sp >> 3, px = sp & 7;
    float acc[8][4];
#pragma unroll
    for (int c = 0; c < 8; c++)
#pragma unroll
        for (int p = 0; p < 4; p++) acc[c][p] = 0.f;
#pragma unroll
    for (int r = 0; r < 9; r++) {
        int ky = r / 3, kx = r % 3;
        int o[4];
        bool v[4];
#pragma unroll
        for (int p = 0; p < 4; p++) {
            int iy = 2 * py + (p >> 1) - 1 + ky;
            int ix = 2 * px + (p & 1) - 1 + kx;
            v[p] = ((unsigned)iy < 16u) && ((unsigned)ix < 16u);
            o[p] = (iy * 16 + ix) * 4;
        }
#pragma unroll 2
        for (int ci4 = 0; ci4 < 4; ci4++) {
            float4 xv[4];
#pragma unroll
            for (int p = 0; p < 4; p++)
                xv[p] = v[p] ? sx[o[p] + ci4] : make_float4(0.f, 0.f, 0.f, 0.f);
#pragma unroll
            for (int c = 0; c < 8; c++) {
                float4 wv = __ldg(&g_w2T4[((co0 + c) * 9 + r) * 4 + ci4]);
#pragma unroll
                for (int p = 0; p < 4; p++) FMA4(acc[c][p], xv[p], wv);
            }
        }
    }
    float* o2 = (float*)(g_a2 + (size_t)img * 512);
#pragma unroll
    for (int c = 0; c < 8; c++) {
        int co = co0 + c;
        float mx = fmaxf(fmaxf(acc[c][0], acc[c][1]), fmaxf(acc[c][2], acc[c][3]));
        float y = __fadd_rn(mx, __ldg(b2c + co));
        o2[sp * 32 + co] = qval_relu(y, s_out);
    }
}

// ---------------------------------------------------------------------------
// conv3: 32->64, 8x8 -> pooled 4x4. Two images/block; warp = co-group of 8;
// lanes = 2 img x 16 sp. Weights warp-uniform via __ldg.
// ---------------------------------------------------------------------------
__global__ __launch_bounds__(256) void conv3_kernel(
    const float* __restrict__ b3c, const float* __restrict__ scl) {
    __shared__ float4 sx[1024];  // 2 img x 512 f4
    int t = threadIdx.x;
    int img0 = blockIdx.x * 2;
    const float4* src = g_a2 + (size_t)img0 * 512;
    for (int i = t; i < 1024; i += 256) sx[i] = src[i];
    __syncthreads();
    float s_out = scl[2];
    int warp = t >> 5, lane = t & 31;
    int co0 = warp * 8;
    int im = lane >> 4, sp = lane & 15;
    int py = sp >> 2, px = sp & 3;
    int base = im * 512;
    float acc[8][4];
#pragma unroll
    for (int c = 0; c < 8; c++)
#pragma unroll
        for (int p = 0; p < 4; p++) acc[c][p] = 0.f;
#pragma unroll
    for (int r = 0; r < 9; r++) {
        int ky = r / 3, kx = r % 3;
        int o[4];
        bool v[4];
#pragma unroll
        for (int p = 0; p < 4; p++) {
            int iy = 2 * py + (p >> 1) - 1 + ky;
            int ix = 2 * px + (p & 1) - 1 + kx;
            v[p] = ((unsigned)iy < 8u) && ((unsigned)ix < 8u);
            o[p] = base + (iy * 8 + ix) * 8;
        }
#pragma unroll 2
        for (int ci4 = 0; ci4 < 8; ci4++) {
            float4 xv[4];
#pragma unroll
            for (int p = 0; p < 4; p++)
                xv[p] = v[p] ? sx[o[p] + ci4] : make_float4(0.f, 0.f, 0.f, 0.f);
#pragma unroll
            for (int c = 0; c < 8; c++) {
                float4 wv = __ldg(&g_w3T4[((co0 + c) * 9 + r) * 8 + ci4]);
#pragma unroll
                for (int p = 0; p < 4; p++) FMA4(acc[c][p], xv[p], wv);
            }
        }
    }
    float* o3 = (float*)(g_a3 + (size_t)(img0 + im) * 256);
#pragma unroll
    for (int c = 0; c < 8; c++) {
        int co = co0 + c;
        float mx = fmaxf(fmaxf(acc[c][0], acc[c][1]), fmaxf(acc[c][2], acc[c][3]));
        float y = __fadd_rn(mx, __ldg(b3c + co));
        o3[sp * 64 + co] = qval_relu(y, s_out);
    }
}

// ---------------------------------------------------------------------------
// conv4: 64->128, 4x4 -> pooled 2x2. Eight images/block; warp = co-group of
// 16 (two 8-co chunks); lanes = 8 img x 4 pooled sp. Weights via __ldg.
// ---------------------------------------------------------------------------
__global__ __launch_bounds__(256) void conv4_kernel(
    const float* __restrict__ b4c, const float* __restrict__ scl) {
    __shared__ float4 sx[2048];  // 8 img x 256 f4 = 32KB
    int t = threadIdx.x;
    int img0 = blockIdx.x * 8;
    const float4* src = g_a3 + (size_t)img0 * 256;
    for (int i = t; i < 2048; i += 256) sx[i] = src[i];
    __syncthreads();
    float s_out = scl[3];
    int warp = t >> 5, lane = t & 31;
    int im = lane >> 2, q = lane & 3;
    int qy = q >> 1, qx = q & 1;
    int base = im * 256;
    float* o4 = (float*)(g_a4 + (size_t)(img0 + im) * 128);
#pragma unroll
    for (int chunk = 0; chunk < 2; chunk++) {
        int co0 = warp * 16 + chunk * 8;
        float acc[8][4];
#pragma unroll
        for (int c = 0; c < 8; c++)
#pragma unroll
            for (int p = 0; p < 4; p++) acc[c][p] = 0.f;
#pragma unroll
        for (int r = 0; r < 9; r++) {
            int ky = r / 3, kx = r % 3;
            int o[4];
            bool v[4];
#pragma unroll
            for (int p = 0; p < 4; p++) {
                int iy = 2 * qy + (p >> 1) - 1 + ky;
                int ix = 2 * qx + (p & 1) - 1 + kx;
                v[p] = ((unsigned)iy < 4u) && ((unsigned)ix < 4u);
                o[p] = base + (iy * 4 + ix) * 16;
            }
#pragma unroll 2
            for (int ci4 = 0; ci4 < 16; ci4++) {
                float4 xv[4];
#pragma unroll
                for (int p = 0; p < 4; p++)
                    xv[p] = v[p] ? sx[o[p] + ci4] : make_float4(0.f, 0.f, 0.f, 0.f);
#pragma unroll
                for (int c = 0; c < 8; c++) {
                    float4 wv = __ldg(&g_w4T4[((co0 + c) * 9 + r) * 16 + ci4]);
#pragma unroll
                    for (int p = 0; p < 4; p++) FMA4(acc[c][p], xv[p], wv);
                }
            }
        }
#pragma unroll
        for (int c = 0; c < 8; c++) {
            int co = co0 + c;
            float mx = fmaxf(fmaxf(acc[c][0], acc[c][1]), fmaxf(acc[c][2], acc[c][3]));
            float y = __fadd_rn(mx, __ldg(b4c + co));
            o4[q * 128 + co] = qval_relu(y, s_out);
        }
    }
}

// ---------------------------------------------------------------------------
// conv5: 128->256, 2x2 -> pooled 1x1. 8 images/block; xv loads are warp
// broadcasts already (cheap); weights via __ldg.
// ---------------------------------------------------------------------------
__global__ __launch_bounds__(256) void conv5_kernel(
    const float* __restrict__ b5c, const float* __restrict__ scl) {
    __shared__ float4 sx[1024];  // 8 img x 128 f4
    int t = threadIdx.x;
    int img0 = blockIdx.x * 8;
    const float4* src = g_a4 + (size_t)img0 * 128;
    for (int i = t; i < 1024; i += 256) sx[i] = src[i];
    __syncthreads();
    float s_out = scl[4];
    int co = t;
    float acc[8][4];
#pragma unroll
    for (int im = 0; im < 8; im++)
#pragma unroll
        for (int p = 0; p < 4; p++) acc[im][p] = 0.f;
#pragma unroll
    for (int r = 0; r < 9; r++) {
        int ky = r / 3, kx = r % 3;
#pragma unroll 2
        for (int ci4 = 0; ci4 < 32; ci4++) {
            float4 wv = __ldg(&g_w5T4[(co * 9 + r) * 32 + ci4]);
#pragma unroll
            for (int im = 0; im < 8; im++) {
#pragma unroll
                for (int p = 0; p < 4; p++) {
                    int iy = (p >> 1) - 1 + ky;
                    int ix = (p & 1) - 1 + kx;
                    if (iy < 0 || iy > 1 || ix < 0 || ix > 1) continue;
                    float4 xv = sx[(im * 4 + (iy * 2 + ix)) * 32 + ci4];
                    FMA4(acc[im][p], xv, wv);
                }
            }
        }
    }
    float b = __ldg(b5c + co);
#pragma unroll
    for (int im = 0; im < 8; im++) {
        float mx = fmaxf(fmaxf(acc[im][0], acc[im][1]), fmaxf(acc[im][2], acc[im][3]));
        float y = __fadd_rn(mx, b);
        g_a5[(size_t)(img0 + im) * 256 + co] = qval_relu(y, s_out);
    }
}

// ---------------------------------------------------------------------------
// head: fc1 (256->512 qrelu) + fc2 (512->43 qid) + softmax. 8 imgs/block.
// ---------------------------------------------------------------------------
__global__ __launch_bounds__(256) void head_kernel(
    const float* __restrict__ bf1c, const float* __restrict__ bf2c,
    const float* __restrict__ scl, float* __restrict__ out, int B) {
    __shared__ float smh[2048 + 4096 + 344];
    float* a5s = smh;          // 8 x 256
    float* f1s = smh + 2048;   // 8 x 512
    float* lg = smh + 6144;    // 8 x 43
    int t = threadIdx.x;
    int img0 = blockIdx.x * 8;
    const float* src = g_a5 + (size_t)img0 * 256;
    for (int i = t; i < 2048; i += 256) a5s[i] = src[i];
    __syncthreads();

    // fc1 (k ascending)
    {
        const float4* a5s4 = (const float4*)a5s;  // [8][64]
        float s_out = scl[5];
#pragma unroll
        for (int rep = 0; rep < 2; rep++) {
            int n = t + rep * 256;
            float acc[8];
#pragma unroll
            for (int im = 0; im < 8; im++) acc[im] = 0.f;
#pragma unroll 4
            for (int k4 = 0; k4 < 64; k4++) {
                float4 wv = __ldg(&g_wf1q4[n * 64 + k4]);
#pragma unroll
                for (int im = 0; im < 8; im++) {
                    float4 xv = a5s4[im * 64 + k4];
                    FMA4(acc[im], xv, wv);
                }
            }
            float b = __ldg(bf1c + n);
#pragma unroll
            for (int im = 0; im < 8; im++) {
                float y = __fadd_rn(acc[im], b);
                f1s[im * 512 + n] = qval_relu(y, s_out);
            }
        }
    }
    __syncthreads();

    // fc2 + quant_identity
    {
        const float4* f1s4 = (const float4*)f1s;  // [8][128]
        float s_out = scl[6];
        if (t < 172) {
            int n = t >> 2, pair = t & 3;
            float a0 = 0.f, a1 = 0.f;
#pragma unroll 4
            for (int k4 = 0; k4 < 128; k4++) {
                float4 wv = __ldg(&g_wf2q4[n * 128 + k4]);
                float4 x0 = f1s4[(pair * 2) * 128 + k4];
                float4 x1 = f1s4[(pair * 2 + 1) * 128 + k4];
                FMA4(a0, x0, wv);
                FMA4(a1, x1, wv);
            }
            float b = __ldg(bf2c + n);
            lg[(pair * 2) * 43 + n] = qval_id(__fadd_rn(a0, b), s_out);
            lg[(pair * 2 + 1) * 43 + n] = qval_id(__fadd_rn(a1, b), s_out);
        }
    }
    __syncthreads();

    // softmax (43 classes, one warp per image)
    {
        int lane = t & 31, w = t >> 5;
        float v0 = lg[w * 43 + lane];
        float v1 = (lane < 11) ? lg[w * 43 + 32 + lane] : -INFINITY;
        float mx = fmaxf(v0, v1);
#pragma unroll
        for (int o = 16; o > 0; o >>= 1) mx = fmaxf(mx, __shfl_xor_sync(0xffffffffu, mx, o));
        float e0 = expf(v0 - mx);
        float e1 = (lane < 11) ? expf(v1 - mx) : 0.f;
        float sum = e0 + e1;
#pragma unroll
        for (int o = 16; o > 0; o >>= 1) sum += __shfl_xor_sync(0xffffffffu, sum, o);
        if ((img0 + w) < B) {
            out[(size_t)(img0 + w) * 43 + lane] = __fdiv_rn(e0, sum);
            if (lane < 11)
                out[(size_t)(img0 + w) * 43 + 32 + lane] = __fdiv_rn(e1, sum);
        }
    }
}

// ---------------------------------------------------------------------------
extern "C" void kernel_launch(void* const* d_in, const int* in_sizes, int n_in,
                              void* d_out, int out_size) {
    const float *x = 0, *w1 = 0, *b1 = 0, *w2 = 0, *b2 = 0, *w3 = 0, *b3 = 0;
    const float *w4 = 0, *b4 = 0, *w5 = 0, *b5 = 0, *wf1 = 0, *bf1 = 0;
    const float *wf2 = 0, *bf2 = 0, *scl = 0;
    int B = 2048;
    for (int i = 0; i < n_in; i++) {
        const float* p = (const float*)d_in[i];
        switch (in_sizes[i]) {
            case 432:    w1 = p;  break;
            case 16:     b1 = p;  break;
            case 4608:   w2 = p;  break;
            case 32:     b2 = p;  break;
            case 18432:  w3 = p;  break;
            case 64:     b3 = p;  break;
            case 73728:  w4 = p;  break;
            case 128:    b4 = p;  break;
            case 294912: w5 = p;  break;
            case 256:    b5 = p;  break;
            case 131072: wf1 = p; break;
            case 512:    bf1 = p; break;
            case 22016:  wf2 = p; break;
            case 43:     bf2 = p; break;
            case 7:      scl = p; break;
            default:     x = p; B = in_sizes[i] / 3072; break;
        }
    }
    float* out = (float*)d_out;

    quant_weights_kernel<<<7, 256>>>(w1, w2, w3, w4, w5, wf1, wf2);
    conv1_kernel<<<B, 256>>>(x, b1, scl);
    conv2_kernel<<<B, 256>>>(b2, scl);
    conv3_kernel<<<B / 2, 256>>>(b3, scl);
    conv4_kernel<<<B / 8, 256>>>(b4, scl);
    conv5_kernel<<<B / 8, 256>>>(b5, scl);
    head_kernel<<<B / 8, 256>>>(bf1, bf2, scl, out, B);
}

// round 12
// speedup vs baseline: 2.0714x; 1.1774x over previous
#include <cuda_runtime.h>
#include <math.h>
#include <stdint.h>

// ---------------------------------------------------------------------------
// TSRNet 4-bit fake-quant CNN — per-layer kernels, reference-order fp32 FMA.
// R12: conv2/3/4 use 16 output channels per warp (acc[16][4]) so each
// activation-window LDS feeds 256 FFMA — halves L1 wavefronts per FMA vs R11.
// Per-accumulator chains keep the exact R8 order (r-major, ci-ascending).
// ---------------------------------------------------------------------------

#define BMAX 2048

__device__ float  g_w1T[16 * 27];            // [co][r][ci], ci=3
__device__ float4 g_w2T4[32 * 9 * 4];        // [co][r][ci4], CI=16
__device__ float4 g_w3T4[64 * 9 * 8];        // CI=32
__device__ float4 g_w4T4[128 * 9 * 16];      // CI=64
__device__ float4 g_w5T4[256 * 9 * 32];      // CI=128
__device__ float4 g_wf1q4[512 * 64];         // [n][k4], K=256
__device__ float4 g_wf2q4[43 * 128];         // K=512

__device__ float4 g_a1[BMAX * 1024];  // [img][256 sp][16ci]/4
__device__ float4 g_a2[BMAX * 512];   // [img][64][32]/4
__device__ float4 g_a3[BMAX * 256];   // [img][16][64]/4
__device__ float4 g_a4[BMAX * 128];   // [img][4][128]/4
__device__ float  g_a5[BMAX * 256];   // [img][256]

__device__ __forceinline__ float qval_relu(float y, float s) {
    float u = __fdiv_rn(y, s);
    float k = rintf(u);
    k = fminf(fmaxf(k, 0.f), 15.f);
    return __fmul_rn(k, s);
}
__device__ __forceinline__ float qval_id(float y, float s) {
    float u = __fdiv_rn(y, s);
    float k = rintf(u);
    k = fminf(fmaxf(k, -8.f), 7.f);
    return __fmul_rn(k, s);
}

#define FMA4(acc, xv, wv)                        \
    do {                                         \
        acc = __fmaf_rn((xv).x, (wv).x, acc);    \
        acc = __fmaf_rn((xv).y, (wv).y, acc);    \
        acc = __fmaf_rn((xv).z, (wv).z, acc);    \
        acc = __fmaf_rn((xv).w, (wv).w, acc);    \
    } while (0)

// ---------------------------------------------------------------------------
// Weight quant (per-tensor symmetric, n=7) + transpose to [co][r][ci].
// ---------------------------------------------------------------------------
__global__ __launch_bounds__(256) void quant_weights_kernel(
    const float* w1, const float* w2, const float* w3, const float* w4,
    const float* w5, const float* wf1, const float* wf2) {
    __shared__ float red[256];
    __shared__ float s_scale;
    const float* src;
    float* dst;
    int n, ci_dim;
    switch (blockIdx.x) {
        case 0: src = w1;  dst = g_w1T;            n = 432;    ci_dim = 3;   break;
        case 1: src = w2;  dst = (float*)g_w2T4;   n = 4608;   ci_dim = 16;  break;
        case 2: src = w3;  dst = (float*)g_w3T4;   n = 18432;  ci_dim = 32;  break;
        case 3: src = w4;  dst = (float*)g_w4T4;   n = 73728;  ci_dim = 64;  break;
        case 4: src = w5;  dst = (float*)g_w5T4;   n = 294912; ci_dim = 128; break;
        case 5: src = wf1; dst = (float*)g_wf1q4;  n = 131072; ci_dim = 0;   break;
        default: src = wf2; dst = (float*)g_wf2q4; n = 22016;  ci_dim = 0;   break;
    }
    int t = threadIdx.x;
    float m = 0.f;
    for (int i = t; i < n; i += 256) m = fmaxf(m, fabsf(src[i]));
    red[t] = m;
    __syncthreads();
    for (int s = 128; s > 0; s >>= 1) {
        if (t < s) red[t] = fmaxf(red[t], red[t + s]);
        __syncthreads();
    }
    if (t == 0) s_scale = __fdiv_rn(red[0], 7.0f);
    __syncthreads();
    float sc = s_scale;
    for (int i = t; i < n; i += 256) {
        float wq = 0.f;
        if (sc > 0.f) {
            float q = rintf(__fdiv_rn(src[i], sc));
            q = fminf(fmaxf(q, -7.f), 7.f);
            wq = __fmul_rn(q, sc);
        }
        if (ci_dim == 0) {
            dst[i] = wq;
        } else {
            int co = i / (ci_dim * 9);
            int rem = i % (ci_dim * 9);
            int ci = rem / 9;
            int r = rem % 9;
            dst[(co * 9 + r) * ci_dim + ci] = wq;
        }
    }
}

// ---------------------------------------------------------------------------
// conv1: 3->16, 32x32 -> pooled 16x16. One image per block (register conv).
// ---------------------------------------------------------------------------
__global__ __launch_bounds__(256) void conv1_kernel(
    const float* __restrict__ x, const float* __restrict__ b1c,
    const float* __restrict__ scl) {
    __shared__ float sxT[3072];  // [32][32][3]
    __shared__ float sw1[432];
    int t = threadIdx.x;
    int img = blockIdx.x;
    for (int i = t; i < 432; i += 256) sw1[i] = g_w1T[i];
    const float* xs = x + (size_t)img * 3072;
    for (int i = t; i < 3072; i += 256) {
        int ci = i >> 10, sp = i & 1023;
        sxT[sp * 3 + ci] = xs[i];
    }
    __syncthreads();
    float s0 = scl[0];
    int py = t >> 4, px = t & 15;
    float win[4][4][3];
#pragma unroll
    for (int wy = 0; wy < 4; wy++) {
        int iy = 2 * py - 1 + wy;
#pragma unroll
        for (int wx = 0; wx < 4; wx++) {
            int ix = 2 * px - 1 + wx;
            bool v = (iy >= 0 && iy < 32 && ix >= 0 && ix < 32);
#pragma unroll
            for (int ci = 0; ci < 3; ci++)
                win[wy][wx][ci] = v ? sxT[(iy * 32 + ix) * 3 + ci] : 0.f;
        }
    }
    float* o = (float*)(g_a1 + (size_t)img * 1024);
#pragma unroll 2
    for (int co = 0; co < 16; co++) {
        float a0 = 0.f, a1 = 0.f, a2 = 0.f, a3 = 0.f;
#pragma unroll
        for (int r = 0; r < 9; r++) {
            int ky = r / 3, kx = r % 3;
#pragma unroll
            for (int ci = 0; ci < 3; ci++) {
                float wv = sw1[co * 27 + r * 3 + ci];
                a0 = __fmaf_rn(win[ky][kx][ci], wv, a0);
                a1 = __fmaf_rn(win[ky][kx + 1][ci], wv, a1);
                a2 = __fmaf_rn(win[ky + 1][kx][ci], wv, a2);
                a3 = __fmaf_rn(win[ky + 1][kx + 1][ci], wv, a3);
            }
        }
        float mx = fmaxf(fmaxf(a0, a1), fmaxf(a2, a3));
        float y = __fadd_rn(mx, __ldg(b1c + co));
        o[(py * 16 + px) * 16 + co] = qval_relu(y, s0);
    }
}

// ---------------------------------------------------------------------------
// conv2: 16->32, 16x16 -> pooled 8x8. 2 images/block; warp = (img, sp-half,
// co-group of 16); lanes = 32 pooled sp. Weights warp-uniform via __ldg.
// ---------------------------------------------------------------------------
__global__ __launch_bounds__(256) void conv2_kernel(
    const float* __restrict__ b2c, const float* __restrict__ scl) {
    __shared__ float4 sx[2048];  // 2 img x 1024 f4 = 32KB
    int t = threadIdx.x;
    int img0 = blockIdx.x * 2;
    const float4* src = g_a1 + (size_t)img0 * 1024;
    for (int i = t; i < 2048; i += 256) sx[i] = src[i];
    __syncthreads();
    float s_out = scl[1];
    int warp = t >> 5, lane = t & 31;
    int im = warp & 1;
    int h = (warp >> 1) & 1;
    int co0 = (warp >> 2) * 16;
    int sp = h * 32 + lane;
    int py = sp >> 3, px = sp & 7;
    int base = im * 1024;
    float acc[16][4];
#pragma unroll
    for (int c = 0; c < 16; c++)
#pragma unroll
        for (int p = 0; p < 4; p++) acc[c][p] = 0.f;
#pragma unroll
    for (int r = 0; r < 9; r++) {
        int ky = r / 3, kx = r % 3;
        int o[4];
        bool v[4];
#pragma unroll
        for (int p = 0; p < 4; p++) {
            int iy = 2 * py + (p >> 1) - 1 + ky;
            int ix = 2 * px + (p & 1) - 1 + kx;
            v[p] = ((unsigned)iy < 16u) && ((unsigned)ix < 16u);
            o[p] = base + (iy * 16 + ix) * 4;
        }
#pragma unroll 2
        for (int ci4 = 0; ci4 < 4; ci4++) {
            float4 xv[4];
#pragma unroll
            for (int p = 0; p < 4; p++)
                xv[p] = v[p] ? sx[o[p] + ci4] : make_float4(0.f, 0.f, 0.f, 0.f);
#pragma unroll
            for (int c = 0; c < 16; c++) {
                float4 wv = __ldg(&g_w2T4[((co0 + c) * 9 + r) * 4 + ci4]);
#pragma unroll
                for (int p = 0; p < 4; p++) FMA4(acc[c][p], xv[p], wv);
            }
        }
    }
    float* o2 = (float*)(g_a2 + (size_t)(img0 + im) * 512);
#pragma unroll
    for (int c = 0; c < 16; c++) {
        int co = co0 + c;
        float mx = fmaxf(fmaxf(acc[c][0], acc[c][1]), fmaxf(acc[c][2], acc[c][3]));
        float y = __fadd_rn(mx, __ldg(b2c + co));
        o2[sp * 32 + co] = qval_relu(y, s_out);
    }
}

// ---------------------------------------------------------------------------
// conv3: 32->64, 8x8 -> pooled 4x4. 4 images/block; warp = (img-pair,
// co-group of 16); lanes = 2 img x 16 sp. Weights warp-uniform via __ldg.
// ---------------------------------------------------------------------------
__global__ __launch_bounds__(256) void conv3_kernel(
    const float* __restrict__ b3c, const float* __restrict__ scl) {
    __shared__ float4 sx[2048];  // 4 img x 512 f4 = 32KB
    int t = threadIdx.x;
    int img0 = blockIdx.x * 4;
    const float4* src = g_a2 + (size_t)img0 * 512;
    for (int i = t; i < 2048; i += 256) sx[i] = src[i];
    __syncthreads();
    float s_out = scl[2];
    int warp = t >> 5, lane = t & 31;
    int p2 = warp & 1;               // image pair
    int co0 = (warp >> 1) * 16;      // 4 co-groups of 16
    int im = lane >> 4, sp = lane & 15;
    int py = sp >> 2, px = sp & 3;
    int base = (p2 * 2 + im) * 512;
    float acc[16][4];
#pragma unroll
    for (int c = 0; c < 16; c++)
#pragma unroll
        for (int p = 0; p < 4; p++) acc[c][p] = 0.f;
#pragma unroll
    for (int r = 0; r < 9; r++) {
        int ky = r / 3, kx = r % 3;
        int o[4];
        bool v[4];
#pragma unroll
        for (int p = 0; p < 4; p++) {
            int iy = 2 * py + (p >> 1) - 1 + ky;
            int ix = 2 * px + (p & 1) - 1 + kx;
            v[p] = ((unsigned)iy < 8u) && ((unsigned)ix < 8u);
            o[p] = base + (iy * 8 + ix) * 8;
        }
#pragma unroll 2
        for (int ci4 = 0; ci4 < 8; ci4++) {
            float4 xv[4];
#pragma unroll
            for (int p = 0; p < 4; p++)
                xv[p] = v[p] ? sx[o[p] + ci4] : make_float4(0.f, 0.f, 0.f, 0.f);
#pragma unroll
            for (int c = 0; c < 16; c++) {
                float4 wv = __ldg(&g_w3T4[((co0 + c) * 9 + r) * 8 + ci4]);
#pragma unroll
                for (int p = 0; p < 4; p++) FMA4(acc[c][p], xv[p], wv);
            }
        }
    }
    float* o3 = (float*)(g_a3 + (size_t)(img0 + p2 * 2 + im) * 256);
#pragma unroll
    for (int c = 0; c < 16; c++) {
        int co = co0 + c;
        float mx = fmaxf(fmaxf(acc[c][0], acc[c][1]), fmaxf(acc[c][2], acc[c][3]));
        float y = __fadd_rn(mx, __ldg(b3c + co));
        o3[sp * 64 + co] = qval_relu(y, s_out);
    }
}

// ---------------------------------------------------------------------------
// conv4: 64->128, 4x4 -> pooled 2x2. 8 images/block; warp = co-group of 16;
// lanes = 8 img x 4 pooled sp. Weights warp-uniform via __ldg.
// ---------------------------------------------------------------------------
__global__ __launch_bounds__(256) void conv4_kernel(
    const float* __restrict__ b4c, const float* __restrict__ scl) {
    __shared__ float4 sx[2048];  // 8 img x 256 f4 = 32KB
    int t = threadIdx.x;
    int img0 = blockIdx.x * 8;
    const float4* src = g_a3 + (size_t)img0 * 256;
    for (int i = t; i < 2048; i += 256) sx[i] = src[i];
    __syncthreads();
    float s_out = scl[3];
    int warp = t >> 5, lane = t & 31;
    int co0 = warp * 16;
    int im = lane >> 2, q = lane & 3;
    int qy = q >> 1, qx = q & 1;
    int base = im * 256;
    float acc[16][4];
#pragma unroll
    for (int c = 0; c < 16; c++)
#pragma unroll
        for (int p = 0; p < 4; p++) acc[c][p] = 0.f;
#pragma unroll
    for (int r = 0; r < 9; r++) {
        int ky = r / 3, kx = r % 3;
        int o[4];
        bool v[4];
#pragma unroll
        for (int p = 0; p < 4; p++) {
            int iy = 2 * qy + (p >> 1) - 1 + ky;
            int ix = 2 * qx + (p & 1) - 1 + kx;
            v[p] = ((unsigned)iy < 4u) && ((unsigned)ix < 4u);
            o[p] = base + (iy * 4 + ix) * 16;
        }
#pragma unroll 1
        for (int ci4 = 0; ci4 < 16; ci4++) {
            float4 xv[4];
#pragma unroll
            for (int p = 0; p < 4; p++)
                xv[p] = v[p] ? sx[o[p] + ci4] : make_float4(0.f, 0.f, 0.f, 0.f);
#pragma unroll
            for (int c = 0; c < 16; c++) {
                float4 wv = __ldg(&g_w4T4[((co0 + c) * 9 + r) * 16 + ci4]);
#pragma unroll
                for (int p = 0; p < 4; p++) FMA4(acc[c][p], xv[p], wv);
            }
        }
    }
    float* o4 = (float*)(g_a4 + (size_t)(img0 + im) * 128);
#pragma unroll
    for (int c = 0; c < 16; c++) {
        int co = co0 + c;
        float mx = fmaxf(fmaxf(acc[c][0], acc[c][1]), fmaxf(acc[c][2], acc[c][3]));
        float y = __fadd_rn(mx, __ldg(b4c + co));
        o4[q * 128 + co] = qval_relu(y, s_out);
    }
}

// ---------------------------------------------------------------------------
// conv5: 128->256, 2x2 -> pooled 1x1. 8 images/block; activation loads are
// warp broadcasts (cheap); weights per-lane via __ldg (L1-hot).
// ---------------------------------------------------------------------------
__global__ __launch_bounds__(256) void conv5_kernel(
    const float* __restrict__ b5c, const float* __restrict__ scl) {
    __shared__ float4 sx[1024];  // 8 img x 128 f4
    int t = threadIdx.x;
    int img0 = blockIdx.x * 8;
    const float4* src = g_a4 + (size_t)img0 * 128;
    for (int i = t; i < 1024; i += 256) sx[i] = src[i];
    __syncthreads();
    float s_out = scl[4];
    int co = t;
    float acc[8][4];
#pragma unroll
    for (int im = 0; im < 8; im++)
#pragma unroll
        for (int p = 0; p < 4; p++) acc[im][p] = 0.f;
#pragma unroll
    for (int r = 0; r < 9; r++) {
        int ky = r / 3, kx = r % 3;
#pragma unroll 2
        for (int ci4 = 0; ci4 < 32; ci4++) {
            float4 wv = __ldg(&g_w5T4[(co * 9 + r) * 32 + ci4]);
#pragma unroll
            for (int im = 0; im < 8; im++) {
#pragma unroll
                for (int p = 0; p < 4; p++) {
                    int iy = (p >> 1) - 1 + ky;
                    int ix = (p & 1) - 1 + kx;
                    if (iy < 0 || iy > 1 || ix < 0 || ix > 1) continue;
                    float4 xv = sx[(im * 4 + (iy * 2 + ix)) * 32 + ci4];
                    FMA4(acc[im][p], xv, wv);
                }
            }
        }
    }
    float b = __ldg(b5c + co);
#pragma unroll
    for (int im = 0; im < 8; im++) {
        float mx = fmaxf(fmaxf(acc[im][0], acc[im][1]), fmaxf(acc[im][2], acc[im][3]));
        float y = __fadd_rn(mx, b);
        g_a5[(size_t)(img0 + im) * 256 + co] = qval_relu(y, s_out);
    }
}

// ---------------------------------------------------------------------------
// head: fc1 (256->512 qrelu) + fc2 (512->43 qid) + softmax. 8 imgs/block.
// ---------------------------------------------------------------------------
__global__ __launch_bounds__(256) void head_kernel(
    const float* __restrict__ bf1c, const float* __restrict__ bf2c,
    const float* __restrict__ scl, float* __restrict__ out, int B) {
    __shared__ float smh[2048 + 4096 + 344];
    float* a5s = smh;          // 8 x 256
    float* f1s = smh + 2048;   // 8 x 512
    float* lg = smh + 6144;    // 8 x 43
    int t = threadIdx.x;
    int img0 = blockIdx.x * 8;
    const float* src = g_a5 + (size_t)img0 * 256;
    for (int i = t; i < 2048; i += 256) a5s[i] = src[i];
    __syncthreads();

    // fc1 (k ascending)
    {
        const float4* a5s4 = (const float4*)a5s;  // [8][64]
        float s_out = scl[5];
#pragma unroll
        for (int rep = 0; rep < 2; rep++) {
            int n = t + rep * 256;
            float acc[8];
#pragma unroll
            for (int im = 0; im < 8; im++) acc[im] = 0.f;
#pragma unroll 4
            for (int k4 = 0; k4 < 64; k4++) {
                float4 wv = __ldg(&g_wf1q4[n * 64 + k4]);
#pragma unroll
                for (int im = 0; im < 8; im++) {
                    float4 xv = a5s4[im * 64 + k4];
                    FMA4(acc[im], xv, wv);
                }
            }
            float b = __ldg(bf1c + n);
#pragma unroll
            for (int im = 0; im < 8; im++) {
                float y = __fadd_rn(acc[im], b);
                f1s[im * 512 + n] = qval_relu(y, s_out);
            }
        }
    }
    __syncthreads();

    // fc2 + quant_identity
    {
        const float4* f1s4 = (const float4*)f1s;  // [8][128]
        float s_out = scl[6];
        if (t < 172) {
            int n = t >> 2, pair = t & 3;
            float a0 = 0.f, a1 = 0.f;
#pragma unroll 4
            for (int k4 = 0; k4 < 128; k4++) {
                float4 wv = __ldg(&g_wf2q4[n * 128 + k4]);
                float4 x0 = f1s4[(pair * 2) * 128 + k4];
                float4 x1 = f1s4[(pair * 2 + 1) * 128 + k4];
                FMA4(a0, x0, wv);
                FMA4(a1, x1, wv);
            }
            float b = __ldg(bf2c + n);
            lg[(pair * 2) * 43 + n] = qval_id(__fadd_rn(a0, b), s_out);
            lg[(pair * 2 + 1) * 43 + n] = qval_id(__fadd_rn(a1, b), s_out);
        }
    }
    __syncthreads();

    // softmax (43 classes, one warp per image)
    {
        int lane = t & 31, w = t >> 5;
        float v0 = lg[w * 43 + lane];
        float v1 = (lane < 11) ? lg[w * 43 + 32 + lane] : -INFINITY;
        float mx = fmaxf(v0, v1);
#pragma unroll
        for (int o = 16; o > 0; o >>= 1) mx = fmaxf(mx, __shfl_xor_sync(0xffffffffu, mx, o));
        float e0 = expf(v0 - mx);
        float e1 = (lane < 11) ? expf(v1 - mx) : 0.f;
        float sum = e0 + e1;
#pragma unroll
        for (int o = 16; o > 0; o >>= 1) sum += __shfl_xor_sync(0xffffffffu, sum, o);
        if ((img0 + w) < B) {
            out[(size_t)(img0 + w) * 43 + lane] = __fdiv_rn(e0, sum);
            if (lane < 11)
                out[(size_t)(img0 + w) * 43 + 32 + lane] = __fdiv_rn(e1, sum);
        }
    }
}

// ---------------------------------------------------------------------------
extern "C" void kernel_launch(void* const* d_in, const int* in_sizes, int n_in,
                              void* d_out, int out_size) {
    const float *x = 0, *w1 = 0, *b1 = 0, *w2 = 0, *b2 = 0, *w3 = 0, *b3 = 0;
    const float *w4 = 0, *b4 = 0, *w5 = 0, *b5 = 0, *wf1 = 0, *bf1 = 0;
    const float *wf2 = 0, *bf2 = 0, *scl = 0;
    int B = 2048;
    for (int i = 0; i < n_in; i++) {
        const float* p = (const float*)d_in[i];
        switch (in_sizes[i]) {
            case 432:    w1 = p;  break;
            case 16:     b1 = p;  break;
            case 4608:   w2 = p;  break;
            case 32:     b2 = p;  break;
            case 18432:  w3 = p;  break;
            case 64:     b3 = p;  break;
            case 73728:  w4 = p;  break;
            case 128:    b4 = p;  break;
            case 294912: w5 = p;  break;
            case 256:    b5 = p;  break;
            case 131072: wf1 = p; break;
            case 512:    bf1 = p; break;
            case 22016:  wf2 = p; break;
            case 43:     bf2 = p; break;
            case 7:      scl = p; break;
            default:     x = p; B = in_sizes[i] / 3072; break;
        }
    }
    float* out = (float*)d_out;

    quant_weights_kernel<<<7, 256>>>(w1, w2, w3, w4, w5, wf1, wf2);
    conv1_kernel<<<B, 256>>>(x, b1, scl);
    conv2_kernel<<<B / 2, 256>>>(b2, scl);
    conv3_kernel<<<B / 4, 256>>>(b3, scl);
    conv4_kernel<<<B / 8, 256>>>(b4, scl);
    conv5_kernel<<<B / 8, 256>>>(b5, scl);
    head_kernel<<<B / 8, 256>>>(bf1, bf2, scl, out, B);
}

// round 13
// speedup vs baseline: 2.1234x; 1.0251x over previous
#include <cuda_runtime.h>
#include <math.h>
#include <stdint.h>

// ---------------------------------------------------------------------------
// TSRNet 4-bit fake-quant CNN — per-layer kernels, reference-order fp32 FMA.
// R13: conv2/3/4 capped at 128 regs (__launch_bounds__(256,2)) for 2 blocks/SM;
// 16 co per warp processed as two 8-co chunks per ci4 step to fit the cap
// without spilling. Per-accumulator chains keep the exact R8 order.
// ---------------------------------------------------------------------------

#define BMAX 2048

__device__ float  g_w1T[16 * 27];            // [co][r][ci], ci=3
__device__ float4 g_w2T4[32 * 9 * 4];        // [co][r][ci4], CI=16
__device__ float4 g_w3T4[64 * 9 * 8];        // CI=32
__device__ float4 g_w4T4[128 * 9 * 16];      // CI=64
__device__ float4 g_w5T4[256 * 9 * 32];      // CI=128
__device__ float4 g_wf1q4[512 * 64];         // [n][k4], K=256
__device__ float4 g_wf2q4[43 * 128];         // K=512

__device__ float4 g_a1[BMAX * 1024];  // [img][256 sp][16ci]/4
__device__ float4 g_a2[BMAX * 512];   // [img][64][32]/4
__device__ float4 g_a3[BMAX * 256];   // [img][16][64]/4
__device__ float4 g_a4[BMAX * 128];   // [img][4][128]/4
__device__ float  g_a5[BMAX * 256];   // [img][256]

__device__ __forceinline__ float qval_relu(float y, float s) {
    float u = __fdiv_rn(y, s);
    float k = rintf(u);
    k = fminf(fmaxf(k, 0.f), 15.f);
    return __fmul_rn(k, s);
}
__device__ __forceinline__ float qval_id(float y, float s) {
    float u = __fdiv_rn(y, s);
    float k = rintf(u);
    k = fminf(fmaxf(k, -8.f), 7.f);
    return __fmul_rn(k, s);
}

#define FMA4(acc, xv, wv)                        \
    do {                                         \
        acc = __fmaf_rn((xv).x, (wv).x, acc);    \
        acc = __fmaf_rn((xv).y, (wv).y, acc);    \
        acc = __fmaf_rn((xv).z, (wv).z, acc);    \
        acc = __fmaf_rn((xv).w, (wv).w, acc);    \
    } while (0)

// ---------------------------------------------------------------------------
// Weight quant (per-tensor symmetric, n=7) + transpose to [co][r][ci].
// ---------------------------------------------------------------------------
__global__ __launch_bounds__(256) void quant_weights_kernel(
    const float* w1, const float* w2, const float* w3, const float* w4,
    const float* w5, const float* wf1, const float* wf2) {
    __shared__ float red[256];
    __shared__ float s_scale;
    const float* src;
    float* dst;
    int n, ci_dim;
    switch (blockIdx.x) {
        case 0: src = w1;  dst = g_w1T;            n = 432;    ci_dim = 3;   break;
        case 1: src = w2;  dst = (float*)g_w2T4;   n = 4608;   ci_dim = 16;  break;
        case 2: src = w3;  dst = (float*)g_w3T4;   n = 18432;  ci_dim = 32;  break;
        case 3: src = w4;  dst = (float*)g_w4T4;   n = 73728;  ci_dim = 64;  break;
        case 4: src = w5;  dst = (float*)g_w5T4;   n = 294912; ci_dim = 128; break;
        case 5: src = wf1; dst = (float*)g_wf1q4;  n = 131072; ci_dim = 0;   break;
        default: src = wf2; dst = (float*)g_wf2q4; n = 22016;  ci_dim = 0;   break;
    }
    int t = threadIdx.x;
    float m = 0.f;
    for (int i = t; i < n; i += 256) m = fmaxf(m, fabsf(src[i]));
    red[t] = m;
    __syncthreads();
    for (int s = 128; s > 0; s >>= 1) {
        if (t < s) red[t] = fmaxf(red[t], red[t + s]);
        __syncthreads();
    }
    if (t == 0) s_scale = __fdiv_rn(red[0], 7.0f);
    __syncthreads();
    float sc = s_scale;
    for (int i = t; i < n; i += 256) {
        float wq = 0.f;
        if (sc > 0.f) {
            float q = rintf(__fdiv_rn(src[i], sc));
            q = fminf(fmaxf(q, -7.f), 7.f);
            wq = __fmul_rn(q, sc);
        }
        if (ci_dim == 0) {
            dst[i] = wq;
        } else {
            int co = i / (ci_dim * 9);
            int rem = i % (ci_dim * 9);
            int ci = rem / 9;
            int r = rem % 9;
            dst[(co * 9 + r) * ci_dim + ci] = wq;
        }
    }
}

// ---------------------------------------------------------------------------
// conv1: 3->16, 32x32 -> pooled 16x16. One image per block (register conv).
// ---------------------------------------------------------------------------
__global__ __launch_bounds__(256) void conv1_kernel(
    const float* __restrict__ x, const float* __restrict__ b1c,
    const float* __restrict__ scl) {
    __shared__ float sxT[3072];  // [32][32][3]
    __shared__ float sw1[432];
    int t = threadIdx.x;
    int img = blockIdx.x;
    for (int i = t; i < 432; i += 256) sw1[i] = g_w1T[i];
    const float* xs = x + (size_t)img * 3072;
    for (int i = t; i < 3072; i += 256) {
        int ci = i >> 10, sp = i & 1023;
        sxT[sp * 3 + ci] = xs[i];
    }
    __syncthreads();
    float s0 = scl[0];
    int py = t >> 4, px = t & 15;
    float win[4][4][3];
#pragma unroll
    for (int wy = 0; wy < 4; wy++) {
        int iy = 2 * py - 1 + wy;
#pragma unroll
        for (int wx = 0; wx < 4; wx++) {
            int ix = 2 * px - 1 + wx;
            bool v = (iy >= 0 && iy < 32 && ix >= 0 && ix < 32);
#pragma unroll
            for (int ci = 0; ci < 3; ci++)
                win[wy][wx][ci] = v ? sxT[(iy * 32 + ix) * 3 + ci] : 0.f;
        }
    }
    float* o = (float*)(g_a1 + (size_t)img * 1024);
#pragma unroll 2
    for (int co = 0; co < 16; co++) {
        float a0 = 0.f, a1 = 0.f, a2 = 0.f, a3 = 0.f;
#pragma unroll
        for (int r = 0; r < 9; r++) {
            int ky = r / 3, kx = r % 3;
#pragma unroll
            for (int ci = 0; ci < 3; ci++) {
                float wv = sw1[co * 27 + r * 3 + ci];
                a0 = __fmaf_rn(win[ky][kx][ci], wv, a0);
                a1 = __fmaf_rn(win[ky][kx + 1][ci], wv, a1);
                a2 = __fmaf_rn(win[ky + 1][kx][ci], wv, a2);
                a3 = __fmaf_rn(win[ky + 1][kx + 1][ci], wv, a3);
            }
        }
        float mx = fmaxf(fmaxf(a0, a1), fmaxf(a2, a3));
        float y = __fadd_rn(mx, __ldg(b1c + co));
        o[(py * 16 + px) * 16 + co] = qval_relu(y, s0);
    }
}

// ---------------------------------------------------------------------------
// conv2: 16->32, 16x16 -> pooled 8x8. 2 images/block; warp = (img, sp-half,
// co-group of 16, two 8-co chunks); lanes = 32 pooled sp.
// ---------------------------------------------------------------------------
__global__ __launch_bounds__(256, 2) void conv2_kernel(
    const float* __restrict__ b2c, const float* __restrict__ scl) {
    __shared__ float4 sx[2048];  // 2 img x 1024 f4 = 32KB
    int t = threadIdx.x;
    int img0 = blockIdx.x * 2;
    const float4* src = g_a1 + (size_t)img0 * 1024;
    for (int i = t; i < 2048; i += 256) sx[i] = src[i];
    __syncthreads();
    float s_out = scl[1];
    int warp = t >> 5, lane = t & 31;
    int im = warp & 1;
    int h = (warp >> 1) & 1;
    int co0 = (warp >> 2) * 16;
    int sp = h * 32 + lane;
    int py = sp >> 3, px = sp & 7;
    int base = im * 1024;
    float acc[16][4];
#pragma unroll
    for (int c = 0; c < 16; c++)
#pragma unroll
        for (int p = 0; p < 4; p++) acc[c][p] = 0.f;
#pragma unroll
    for (int r = 0; r < 9; r++) {
        int ky = r / 3, kx = r % 3;
        int o[4];
        bool v[4];
#pragma unroll
        for (int p = 0; p < 4; p++) {
            int iy = 2 * py + (p >> 1) - 1 + ky;
            int ix = 2 * px + (p & 1) - 1 + kx;
            v[p] = ((unsigned)iy < 16u) && ((unsigned)ix < 16u);
            o[p] = base + (iy * 16 + ix) * 4;
        }
#pragma unroll 2
        for (int ci4 = 0; ci4 < 4; ci4++) {
            float4 xv[4];
#pragma unroll
            for (int p = 0; p < 4; p++)
                xv[p] = v[p] ? sx[o[p] + ci4] : make_float4(0.f, 0.f, 0.f, 0.f);
#pragma unroll
            for (int ch = 0; ch < 2; ch++) {
#pragma unroll
                for (int c = 0; c < 8; c++) {
                    int cc = ch * 8 + c;
                    float4 wv = __ldg(&g_w2T4[((co0 + cc) * 9 + r) * 4 + ci4]);
#pragma unroll
                    for (int p = 0; p < 4; p++) FMA4(acc[cc][p], xv[p], wv);
                }
            }
        }
    }
    float* o2 = (float*)(g_a2 + (size_t)(img0 + im) * 512);
#pragma unroll
    for (int c = 0; c < 16; c++) {
        int co = co0 + c;
        float mx = fmaxf(fmaxf(acc[c][0], acc[c][1]), fmaxf(acc[c][2], acc[c][3]));
        float y = __fadd_rn(mx, __ldg(b2c + co));
        o2[sp * 32 + co] = qval_relu(y, s_out);
    }
}

// ---------------------------------------------------------------------------
// conv3: 32->64, 8x8 -> pooled 4x4. 4 images/block; warp = (img-pair,
// co-group of 16, two 8-co chunks); lanes = 2 img x 16 sp.
// ---------------------------------------------------------------------------
__global__ __launch_bounds__(256, 2) void conv3_kernel(
    const float* __restrict__ b3c, const float* __restrict__ scl) {
    __shared__ float4 sx[2048];  // 4 img x 512 f4 = 32KB
    int t = threadIdx.x;
    int img0 = blockIdx.x * 4;
    const float4* src = g_a2 + (size_t)img0 * 512;
    for (int i = t; i < 2048; i += 256) sx[i] = src[i];
    __syncthreads();
    float s_out = scl[2];
    int warp = t >> 5, lane = t & 31;
    int p2 = warp & 1;               // image pair
    int co0 = (warp >> 1) * 16;      // 4 co-groups of 16
    int im = lane >> 4, sp = lane & 15;
    int py = sp >> 2, px = sp & 3;
    int base = (p2 * 2 + im) * 512;
    float acc[16][4];
#pragma unroll
    for (int c = 0; c < 16; c++)
#pragma unroll
        for (int p = 0; p < 4; p++) acc[c][p] = 0.f;
#pragma unroll
    for (int r = 0; r < 9; r++) {
        int ky = r / 3, kx = r % 3;
        int o[4];
        bool v[4];
#pragma unroll
        for (int p = 0; p < 4; p++) {
            int iy = 2 * py + (p >> 1) - 1 + ky;
            int ix = 2 * px + (p & 1) - 1 + kx;
            v[p] = ((unsigned)iy < 8u) && ((unsigned)ix < 8u);
            o[p] = base + (iy * 8 + ix) * 8;
        }
#pragma unroll 2
        for (int ci4 = 0; ci4 < 8; ci4++) {
            float4 xv[4];
#pragma unroll
            for (int p = 0; p < 4; p++)
                xv[p] = v[p] ? sx[o[p] + ci4] : make_float4(0.f, 0.f, 0.f, 0.f);
#pragma unroll
            for (int ch = 0; ch < 2; ch++) {
#pragma unroll
                for (int c = 0; c < 8; c++) {
                    int cc = ch * 8 + c;
                    float4 wv = __ldg(&g_w3T4[((co0 + cc) * 9 + r) * 8 + ci4]);
#pragma unroll
                    for (int p = 0; p < 4; p++) FMA4(acc[cc][p], xv[p], wv);
                }
            }
        }
    }
    float* o3 = (float*)(g_a3 + (size_t)(img0 + p2 * 2 + im) * 256);
#pragma unroll
    for (int c = 0; c < 16; c++) {
        int co = co0 + c;
        float mx = fmaxf(fmaxf(acc[c][0], acc[c][1]), fmaxf(acc[c][2], acc[c][3]));
        float y = __fadd_rn(mx, __ldg(b3c + co));
        o3[sp * 64 + co] = qval_relu(y, s_out);
    }
}

// ---------------------------------------------------------------------------
// conv4: 64->128, 4x4 -> pooled 2x2. 8 images/block; warp = co-group of 16
// (two 8-co chunks); lanes = 8 img x 4 pooled sp.
// ---------------------------------------------------------------------------
__global__ __launch_bounds__(256, 2) void conv4_kernel(
    const float* __restrict__ b4c, const float* __restrict__ scl) {
    __shared__ float4 sx[2048];  // 8 img x 256 f4 = 32KB
    int t = threadIdx.x;
    int img0 = blockIdx.x * 8;
    const float4* src = g_a3 + (size_t)img0 * 256;
    for (int i = t; i < 2048; i += 256) sx[i] = src[i];
    __syncthreads();
    float s_out = scl[3];
    int warp = t >> 5, lane = t & 31;
    int co0 = warp * 16;
    int im = lane >> 2, q = lane & 3;
    int qy = q >> 1, qx = q & 1;
    int base = im * 256;
    float acc[16][4];
#pragma unroll
    for (int c = 0; c < 16; c++)
#pragma unroll
        for (int p = 0; p < 4; p++) acc[c][p] = 0.f;
#pragma unroll
    for (int r = 0; r < 9; r++) {
        int ky = r / 3, kx = r % 3;
        int o[4];
        bool v[4];
#pragma unroll
        for (int p = 0; p < 4; p++) {
            int iy = 2 * qy + (p >> 1) - 1 + ky;
            int ix = 2 * qx + (p & 1) - 1 + kx;
            v[p] = ((unsigned)iy < 4u) && ((unsigned)ix < 4u);
            o[p] = base + (iy * 4 + ix) * 16;
        }
#pragma unroll 1
        for (int ci4 = 0; ci4 < 16; ci4++) {
            float4 xv[4];
#pragma unroll
            for (int p = 0; p < 4; p++)
                xv[p] = v[p] ? sx[o[p] + ci4] : make_float4(0.f, 0.f, 0.f, 0.f);
#pragma unroll
            for (int ch = 0; ch < 2; ch++) {
#pragma unroll
                for (int c = 0; c < 8; c++) {
                    int cc = ch * 8 + c;
                    float4 wv = __ldg(&g_w4T4[((co0 + cc) * 9 + r) * 16 + ci4]);
#pragma unroll
                    for (int p = 0; p < 4; p++) FMA4(acc[cc][p], xv[p], wv);
                }
            }
        }
    }
    float* o4 = (float*)(g_a4 + (size_t)(img0 + im) * 128);
#pragma unroll
    for (int c = 0; c < 16; c++) {
        int co = co0 + c;
        float mx = fmaxf(fmaxf(acc[c][0], acc[c][1]), fmaxf(acc[c][2], acc[c][3]));
        float y = __fadd_rn(mx, __ldg(b4c + co));
        o4[q * 128 + co] = qval_relu(y, s_out);
    }
}

// ---------------------------------------------------------------------------
// conv5: 128->256, 2x2 -> pooled 1x1. 8 images/block; activation loads are
// warp broadcasts (cheap); weights per-lane via __ldg (L1-hot).
// ---------------------------------------------------------------------------
__global__ __launch_bounds__(256) void conv5_kernel(
    const float* __restrict__ b5c, const float* __restrict__ scl) {
    __shared__ float4 sx[1024];  // 8 img x 128 f4
    int t = threadIdx.x;
    int img0 = blockIdx.x * 8;
    const float4* src = g_a4 + (size_t)img0 * 128;
    for (int i = t; i < 1024; i += 256) sx[i] = src[i];
    __syncthreads();
    float s_out = scl[4];
    int co = t;
    float acc[8][4];
#pragma unroll
    for (int im = 0; im < 8; im++)
#pragma unroll
        for (int p = 0; p < 4; p++) acc[im][p] = 0.f;
#pragma unroll
    for (int r = 0; r < 9; r++) {
        int ky = r / 3, kx = r % 3;
#pragma unroll 2
        for (int ci4 = 0; ci4 < 32; ci4++) {
            float4 wv = __ldg(&g_w5T4[(co * 9 + r) * 32 + ci4]);
#pragma unroll
            for (int im = 0; im < 8; im++) {
#pragma unroll
                for (int p = 0; p < 4; p++) {
                    int iy = (p >> 1) - 1 + ky;
                    int ix = (p & 1) - 1 + kx;
                    if (iy < 0 || iy > 1 || ix < 0 || ix > 1) continue;
                    float4 xv = sx[(im * 4 + (iy * 2 + ix)) * 32 + ci4];
                    FMA4(acc[im][p], xv, wv);
                }
            }
        }
    }
    float b = __ldg(b5c + co);
#pragma unroll
    for (int im = 0; im < 8; im++) {
        float mx = fmaxf(fmaxf(acc[im][0], acc[im][1]), fmaxf(acc[im][2], acc[im][3]));
        float y = __fadd_rn(mx, b);
        g_a5[(size_t)(img0 + im) * 256 + co] = qval_relu(y, s_out);
    }
}

// ---------------------------------------------------------------------------
// head: fc1 (256->512 qrelu) + fc2 (512->43 qid) + softmax. 8 imgs/block.
// ---------------------------------------------------------------------------
__global__ __launch_bounds__(256) void head_kernel(
    const float* __restrict__ bf1c, const float* __restrict__ bf2c,
    const float* __restrict__ scl, float* __restrict__ out, int B) {
    __shared__ float smh[2048 + 4096 + 344];
    float* a5s = smh;          // 8 x 256
    float* f1s = smh + 2048;   // 8 x 512
    float* lg = smh + 6144;    // 8 x 43
    int t = threadIdx.x;
    int img0 = blockIdx.x * 8;
    const float* src = g_a5 + (size_t)img0 * 256;
    for (int i = t; i < 2048; i += 256) a5s[i] = src[i];
    __syncthreads();

    // fc1 (k ascending)
    {
        const float4* a5s4 = (const float4*)a5s;  // [8][64]
        float s_out = scl[5];
#pragma unroll
        for (int rep = 0; rep < 2; rep++) {
            int n = t + rep * 256;
            float acc[8];
#pragma unroll
            for (int im = 0; im < 8; im++) acc[im] = 0.f;
#pragma unroll 4
            for (int k4 = 0; k4 < 64; k4++) {
                float4 wv = __ldg(&g_wf1q4[n * 64 + k4]);
#pragma unroll
                for (int im = 0; im < 8; im++) {
                    float4 xv = a5s4[im * 64 + k4];
                    FMA4(acc[im], xv, wv);
                }
            }
            float b = __ldg(bf1c + n);
#pragma unroll
            for (int im = 0; im < 8; im++) {
                float y = __fadd_rn(acc[im], b);
                f1s[im * 512 + n] = qval_relu(y, s_out);
            }
        }
    }
    __syncthreads();

    // fc2 + quant_identity
    {
        const float4* f1s4 = (const float4*)f1s;  // [8][128]
        float s_out = scl[6];
        if (t < 172) {
            int n = t >> 2, pair = t & 3;
            float a0 = 0.f, a1 = 0.f;
#pragma unroll 4
            for (int k4 = 0; k4 < 128; k4++) {
                float4 wv = __ldg(&g_wf2q4[n * 128 + k4]);
                float4 x0 = f1s4[(pair * 2) * 128 + k4];
                float4 x1 = f1s4[(pair * 2 + 1) * 128 + k4];
                FMA4(a0, x0, wv);
                FMA4(a1, x1, wv);
            }
            float b = __ldg(bf2c + n);
            lg[(pair * 2) * 43 + n] = qval_id(__fadd_rn(a0, b), s_out);
            lg[(pair * 2 + 1) * 43 + n] = qval_id(__fadd_rn(a1, b), s_out);
        }
    }
    __syncthreads();

    // softmax (43 classes, one warp per image)
    {
        int lane = t & 31, w = t >> 5;
        float v0 = lg[w * 43 + lane];
        float v1 = (lane < 11) ? lg[w * 43 + 32 + lane] : -INFINITY;
        float mx = fmaxf(v0, v1);
#pragma unroll
        for (int o = 16; o > 0; o >>= 1) mx = fmaxf(mx, __shfl_xor_sync(0xffffffffu, mx, o));
        float e0 = expf(v0 - mx);
        float e1 = (lane < 11) ? expf(v1 - mx) : 0.f;
        float sum = e0 + e1;
#pragma unroll
        for (int o = 16; o > 0; o >>= 1) sum += __shfl_xor_sync(0xffffffffu, sum, o);
        if ((img0 + w) < B) {
            out[(size_t)(img0 + w) * 43 + lane] = __fdiv_rn(e0, sum);
            if (lane < 11)
                out[(size_t)(img0 + w) * 43 + 32 + lane] = __fdiv_rn(e1, sum);
        }
    }
}

// ---------------------------------------------------------------------------
extern "C" void kernel_launch(void* const* d_in, const int* in_sizes, int n_in,
                              void* d_out, int out_size) {
    const float *x = 0, *w1 = 0, *b1 = 0, *w2 = 0, *b2 = 0, *w3 = 0, *b3 = 0;
    const float *w4 = 0, *b4 = 0, *w5 = 0, *b5 = 0, *wf1 = 0, *bf1 = 0;
    const float *wf2 = 0, *bf2 = 0, *scl = 0;
    int B = 2048;
    for (int i = 0; i < n_in; i++) {
        const float* p = (const float*)d_in[i];
        switch (in_sizes[i]) {
            case 432:    w1 = p;  break;
            case 16:     b1 = p;  break;
            case 4608:   w2 = p;  break;
            case 32:     b2 = p;  break;
            case 18432:  w3 = p;  break;
            case 64:     b3 = p;  break;
            case 73728:  w4 = p;  break;
            case 128:    b4 = p;  break;
            case 294912: w5 = p;  break;
            case 256:    b5 = p;  break;
            case 131072: wf1 = p; break;
            case 512:    bf1 = p; break;
            case 22016:  wf2 = p; break;
            case 43:     bf2 = p; break;
            case 7:      scl = p; break;
            default:     x = p; B = in_sizes[i] / 3072; break;
        }
    }
    float* out = (float*)d_out;

    quant_weights_kernel<<<7, 256>>>(w1, w2, w3, w4, w5, wf1, wf2);
    conv1_kernel<<<B, 256>>>(x, b1, scl);
    conv2_kernel<<<B / 2, 256>>>(b2, scl);
    conv3_kernel<<<B / 4, 256>>>(b3, scl);
    conv4_kernel<<<B / 8, 256>>>(b4, scl);
    conv5_kernel<<<B / 8, 256>>>(b5, scl);
    head_kernel<<<B / 8, 256>>>(bf1, bf2, scl, out, B);
}

// round 14
// speedup vs baseline: 2.4408x; 1.1495x over previous
#include <cuda_runtime.h>
#include <math.h>
#include <stdint.h>

// ---------------------------------------------------------------------------
// TSRNet 4-bit fake-quant CNN — per-layer kernels, reference-order fp32 FMA.
// R14: SMEM activation tiles padded to ODD 16B-group row stride (conv2 5,
// conv3 9, conv4 17 float4s per spatial position) -> bank-conflict-free
// LDS.128 (previous power-of-two strides put every lane on one 4-bank group).
// FMA chains byte-identical to R8 (r-major, ci-ascending).
// ---------------------------------------------------------------------------

#define BMAX 2048

__device__ float  g_w1T[16 * 27];            // [co][r][ci], ci=3
__device__ float4 g_w2T4[32 * 9 * 4];        // [co][r][ci4], CI=16
__device__ float4 g_w3T4[64 * 9 * 8];        // CI=32
__device__ float4 g_w4T4[128 * 9 * 16];      // CI=64
__device__ float4 g_w5T4[256 * 9 * 32];      // CI=128
__device__ float4 g_wf1q4[512 * 64];         // [n][k4], K=256
__device__ float4 g_wf2q4[43 * 128];         // K=512

__device__ float4 g_a1[BMAX * 1024];  // [img][256 sp][16ci]/4
__device__ float4 g_a2[BMAX * 512];   // [img][64][32]/4
__device__ float4 g_a3[BMAX * 256];   // [img][16][64]/4
__device__ float4 g_a4[BMAX * 128];   // [img][4][128]/4
__device__ float  g_a5[BMAX * 256];   // [img][256]

__device__ __forceinline__ float qval_relu(float y, float s) {
    float u = __fdiv_rn(y, s);
    float k = rintf(u);
    k = fminf(fmaxf(k, 0.f), 15.f);
    return __fmul_rn(k, s);
}
__device__ __forceinline__ float qval_id(float y, float s) {
    float u = __fdiv_rn(y, s);
    float k = rintf(u);
    k = fminf(fmaxf(k, -8.f), 7.f);
    return __fmul_rn(k, s);
}

#define FMA4(acc, xv, wv)                        \
    do {                                         \
        acc = __fmaf_rn((xv).x, (wv).x, acc);    \
        acc = __fmaf_rn((xv).y, (wv).y, acc);    \
        acc = __fmaf_rn((xv).z, (wv).z, acc);    \
        acc = __fmaf_rn((xv).w, (wv).w, acc);    \
    } while (0)

// ---------------------------------------------------------------------------
// Weight quant (per-tensor symmetric, n=7) + transpose to [co][r][ci].
// ---------------------------------------------------------------------------
__global__ __launch_bounds__(256) void quant_weights_kernel(
    const float* w1, const float* w2, const float* w3, const float* w4,
    const float* w5, const float* wf1, const float* wf2) {
    __shared__ float red[256];
    __shared__ float s_scale;
    const float* src;
    float* dst;
    int n, ci_dim;
    switch (blockIdx.x) {
        case 0: src = w1;  dst = g_w1T;            n = 432;    ci_dim = 3;   break;
        case 1: src = w2;  dst = (float*)g_w2T4;   n = 4608;   ci_dim = 16;  break;
        case 2: src = w3;  dst = (float*)g_w3T4;   n = 18432;  ci_dim = 32;  break;
        case 3: src = w4;  dst = (float*)g_w4T4;   n = 73728;  ci_dim = 64;  break;
        case 4: src = w5;  dst = (float*)g_w5T4;   n = 294912; ci_dim = 128; break;
        case 5: src = wf1; dst = (float*)g_wf1q4;  n = 131072; ci_dim = 0;   break;
        default: src = wf2; dst = (float*)g_wf2q4; n = 22016;  ci_dim = 0;   break;
    }
    int t = threadIdx.x;
    float m = 0.f;
    for (int i = t; i < n; i += 256) m = fmaxf(m, fabsf(src[i]));
    red[t] = m;
    __syncthreads();
    for (int s = 128; s > 0; s >>= 1) {
        if (t < s) red[t] = fmaxf(red[t], red[t + s]);
        __syncthreads();
    }
    if (t == 0) s_scale = __fdiv_rn(red[0], 7.0f);
    __syncthreads();
    float sc = s_scale;
    for (int i = t; i < n; i += 256) {
        float wq = 0.f;
        if (sc > 0.f) {
            float q = rintf(__fdiv_rn(src[i], sc));
            q = fminf(fmaxf(q, -7.f), 7.f);
            wq = __fmul_rn(q, sc);
        }
        if (ci_dim == 0) {
            dst[i] = wq;
        } else {
            int co = i / (ci_dim * 9);
            int rem = i % (ci_dim * 9);
            int ci = rem / 9;
            int r = rem % 9;
            dst[(co * 9 + r) * ci_dim + ci] = wq;
        }
    }
}

// ---------------------------------------------------------------------------
// conv1: 3->16, 32x32 -> pooled 16x16. One image per block (register conv).
// ---------------------------------------------------------------------------
__global__ __launch_bounds__(256) void conv1_kernel(
    const float* __restrict__ x, const float* __restrict__ b1c,
    const float* __restrict__ scl) {
    __shared__ float sxT[3072];  // [32][32][3]
    __shared__ float sw1[432];
    int t = threadIdx.x;
    int img = blockIdx.x;
    for (int i = t; i < 432; i += 256) sw1[i] = g_w1T[i];
    const float* xs = x + (size_t)img * 3072;
    for (int i = t; i < 3072; i += 256) {
        int ci = i >> 10, sp = i & 1023;
        sxT[sp * 3 + ci] = xs[i];
    }
    __syncthreads();
    float s0 = scl[0];
    int py = t >> 4, px = t & 15;
    float win[4][4][3];
#pragma unroll
    for (int wy = 0; wy < 4; wy++) {
        int iy = 2 * py - 1 + wy;
#pragma unroll
        for (int wx = 0; wx < 4; wx++) {
            int ix = 2 * px - 1 + wx;
            bool v = (iy >= 0 && iy < 32 && ix >= 0 && ix < 32);
#pragma unroll
            for (int ci = 0; ci < 3; ci++)
                win[wy][wx][ci] = v ? sxT[(iy * 32 + ix) * 3 + ci] : 0.f;
        }
    }
    float* o = (float*)(g_a1 + (size_t)img * 1024);
#pragma unroll 2
    for (int co = 0; co < 16; co++) {
        float a0 = 0.f, a1 = 0.f, a2 = 0.f, a3 = 0.f;
#pragma unroll
        for (int r = 0; r < 9; r++) {
            int ky = r / 3, kx = r % 3;
#pragma unroll
            for (int ci = 0; ci < 3; ci++) {
                float wv = sw1[co * 27 + r * 3 + ci];
                a0 = __fmaf_rn(win[ky][kx][ci], wv, a0);
                a1 = __fmaf_rn(win[ky][kx + 1][ci], wv, a1);
                a2 = __fmaf_rn(win[ky + 1][kx][ci], wv, a2);
                a3 = __fmaf_rn(win[ky + 1][kx + 1][ci], wv, a3);
            }
        }
        float mx = fmaxf(fmaxf(a0, a1), fmaxf(a2, a3));
        float y = __fadd_rn(mx, __ldg(b1c + co));
        o[(py * 16 + px) * 16 + co] = qval_relu(y, s0);
    }
}

// ---------------------------------------------------------------------------
// conv2: 16->32, 16x16 -> pooled 8x8. 2 images/block. SMEM row stride 5 f4
// (odd -> conflict-free). Warp = (img, sp-half, co-16 in two 8-chunks).
// ---------------------------------------------------------------------------
__global__ __launch_bounds__(256, 2) void conv2_kernel(
    const float* __restrict__ b2c, const float* __restrict__ scl) {
    __shared__ float4 sx[2560];  // 2 img x 256 sp x 5 f4 = 40KB
    int t = threadIdx.x;
    int img0 = blockIdx.x * 2;
    const float4* src = g_a1 + (size_t)img0 * 1024;
    for (int i = t; i < 2048; i += 256) {
        int img = i >> 10, rem = i & 1023;
        int sp = rem >> 2, ci4 = rem & 3;
        sx[img * 1280 + sp * 5 + ci4] = src[i];
    }
    __syncthreads();
    float s_out = scl[1];
    int warp = t >> 5, lane = t & 31;
    int im = warp & 1;
    int h = (warp >> 1) & 1;
    int co0 = (warp >> 2) * 16;
    int sp = h * 32 + lane;
    int py = sp >> 3, px = sp & 7;
    int base = im * 1280;
    float acc[16][4];
#pragma unroll
    for (int c = 0; c < 16; c++)
#pragma unroll
        for (int p = 0; p < 4; p++) acc[c][p] = 0.f;
#pragma unroll
    for (int r = 0; r < 9; r++) {
        int ky = r / 3, kx = r % 3;
        int o[4];
        bool v[4];
#pragma unroll
        for (int p = 0; p < 4; p++) {
            int iy = 2 * py + (p >> 1) - 1 + ky;
            int ix = 2 * px + (p & 1) - 1 + kx;
            v[p] = ((unsigned)iy < 16u) && ((unsigned)ix < 16u);
            o[p] = base + (iy * 16 + ix) * 5;
        }
#pragma unroll 2
        for (int ci4 = 0; ci4 < 4; ci4++) {
            float4 xv[4];
#pragma unroll
            for (int p = 0; p < 4; p++)
                xv[p] = v[p] ? sx[o[p] + ci4] : make_float4(0.f, 0.f, 0.f, 0.f);
#pragma unroll
            for (int ch = 0; ch < 2; ch++) {
#pragma unroll
                for (int c = 0; c < 8; c++) {
                    int cc = ch * 8 + c;
                    float4 wv = __ldg(&g_w2T4[((co0 + cc) * 9 + r) * 4 + ci4]);
#pragma unroll
                    for (int p = 0; p < 4; p++) FMA4(acc[cc][p], xv[p], wv);
                }
            }
        }
    }
    float* o2 = (float*)(g_a2 + (size_t)(img0 + im) * 512);
#pragma unroll
    for (int c = 0; c < 16; c++) {
        int co = co0 + c;
        float mx = fmaxf(fmaxf(acc[c][0], acc[c][1]), fmaxf(acc[c][2], acc[c][3]));
        float y = __fadd_rn(mx, __ldg(b2c + co));
        o2[sp * 32 + co] = qval_relu(y, s_out);
    }
}

// ---------------------------------------------------------------------------
// conv3: 32->64, 8x8 -> pooled 4x4. 4 images/block. SMEM row stride 9 f4.
// ---------------------------------------------------------------------------
__global__ __launch_bounds__(256, 2) void conv3_kernel(
    const float* __restrict__ b3c, const float* __restrict__ scl) {
    __shared__ float4 sx[2304];  // 4 img x 64 sp x 9 f4 = 36KB
    int t = threadIdx.x;
    int img0 = blockIdx.x * 4;
    const float4* src = g_a2 + (size_t)img0 * 512;
    for (int i = t; i < 2048; i += 256) {
        int img = i >> 9, rem = i & 511;
        int sp = rem >> 3, ci4 = rem & 7;
        sx[img * 576 + sp * 9 + ci4] = src[i];
    }
    __syncthreads();
    float s_out = scl[2];
    int warp = t >> 5, lane = t & 31;
    int p2 = warp & 1;               // image pair
    int co0 = (warp >> 1) * 16;      // 4 co-groups of 16
    int im = lane >> 4, sp = lane & 15;
    int py = sp >> 2, px = sp & 3;
    int base = (p2 * 2 + im) * 576;
    float acc[16][4];
#pragma unroll
    for (int c = 0; c < 16; c++)
#pragma unroll
        for (int p = 0; p < 4; p++) acc[c][p] = 0.f;
#pragma unroll
    for (int r = 0; r < 9; r++) {
        int ky = r / 3, kx = r % 3;
        int o[4];
        bool v[4];
#pragma unroll
        for (int p = 0; p < 4; p++) {
            int iy = 2 * py + (p >> 1) - 1 + ky;
            int ix = 2 * px + (p & 1) - 1 + kx;
            v[p] = ((unsigned)iy < 8u) && ((unsigned)ix < 8u);
            o[p] = base + (iy * 8 + ix) * 9;
        }
#pragma unroll 2
        for (int ci4 = 0; ci4 < 8; ci4++) {
            float4 xv[4];
#pragma unroll
            for (int p = 0; p < 4; p++)
                xv[p] = v[p] ? sx[o[p] + ci4] : make_float4(0.f, 0.f, 0.f, 0.f);
#pragma unroll
            for (int ch = 0; ch < 2; ch++) {
#pragma unroll
                for (int c = 0; c < 8; c++) {
                    int cc = ch * 8 + c;
                    float4 wv = __ldg(&g_w3T4[((co0 + cc) * 9 + r) * 8 + ci4]);
#pragma unroll
                    for (int p = 0; p < 4; p++) FMA4(acc[cc][p], xv[p], wv);
                }
            }
        }
    }
    float* o3 = (float*)(g_a3 + (size_t)(img0 + p2 * 2 + im) * 256);
#pragma unroll
    for (int c = 0; c < 16; c++) {
        int co = co0 + c;
        float mx = fmaxf(fmaxf(acc[c][0], acc[c][1]), fmaxf(acc[c][2], acc[c][3]));
        float y = __fadd_rn(mx, __ldg(b3c + co));
        o3[sp * 64 + co] = qval_relu(y, s_out);
    }
}

// ---------------------------------------------------------------------------
// conv4: 64->128, 4x4 -> pooled 2x2. 8 images/block. SMEM row stride 17 f4.
// ---------------------------------------------------------------------------
__global__ __launch_bounds__(256, 2) void conv4_kernel(
    const float* __restrict__ b4c, const float* __restrict__ scl) {
    __shared__ float4 sx[2176];  // 8 img x 16 sp x 17 f4 = 34KB
    int t = threadIdx.x;
    int img0 = blockIdx.x * 8;
    const float4* src = g_a3 + (size_t)img0 * 256;
    for (int i = t; i < 2048; i += 256) {
        int img = i >> 8, rem = i & 255;
        int sp = rem >> 4, ci4 = rem & 15;
        sx[img * 272 + sp * 17 + ci4] = src[i];
    }
    __syncthreads();
    float s_out = scl[3];
    int warp = t >> 5, lane = t & 31;
    int co0 = warp * 16;
    int im = lane >> 2, q = lane & 3;
    int qy = q >> 1, qx = q & 1;
    int base = im * 272;
    float acc[16][4];
#pragma unroll
    for (int c = 0; c < 16; c++)
#pragma unroll
        for (int p = 0; p < 4; p++) acc[c][p] = 0.f;
#pragma unroll
    for (int r = 0; r < 9; r++) {
        int ky = r / 3, kx = r % 3;
        int o[4];
        bool v[4];
#pragma unroll
        for (int p = 0; p < 4; p++) {
            int iy = 2 * qy + (p >> 1) - 1 + ky;
            int ix = 2 * qx + (p & 1) - 1 + kx;
            v[p] = ((unsigned)iy < 4u) && ((unsigned)ix < 4u);
            o[p] = base + (iy * 4 + ix) * 17;
        }
#pragma unroll 1
        for (int ci4 = 0; ci4 < 16; ci4++) {
            float4 xv[4];
#pragma unroll
            for (int p = 0; p < 4; p++)
                xv[p] = v[p] ? sx[o[p] + ci4] : make_float4(0.f, 0.f, 0.f, 0.f);
#pragma unroll
            for (int ch = 0; ch < 2; ch++) {
#pragma unroll
                for (int c = 0; c < 8; c++) {
                    int cc = ch * 8 + c;
                    float4 wv = __ldg(&g_w4T4[((co0 + cc) * 9 + r) * 16 + ci4]);
#pragma unroll
                    for (int p = 0; p < 4; p++) FMA4(acc[cc][p], xv[p], wv);
                }
            }
        }
    }
    float* o4 = (float*)(g_a4 + (size_t)(img0 + im) * 128);
#pragma unroll
    for (int c = 0; c < 16; c++) {
        int co = co0 + c;
        float mx = fmaxf(fmaxf(acc[c][0], acc[c][1]), fmaxf(acc[c][2], acc[c][3]));
        float y = __fadd_rn(mx, __ldg(b4c + co));
        o4[q * 128 + co] = qval_relu(y, s_out);
    }
}

// ---------------------------------------------------------------------------
// conv5: 128->256, 2x2 -> pooled 1x1. 8 images/block; activation loads are
// warp broadcasts (conflict-free); weights per-lane via __ldg (L1-hot).
// ---------------------------------------------------------------------------
__global__ __launch_bounds__(256) void conv5_kernel(
    const float* __restrict__ b5c, const float* __restrict__ scl) {
    __shared__ float4 sx[1024];  // 8 img x 128 f4
    int t = threadIdx.x;
    int img0 = blockIdx.x * 8;
    const float4* src = g_a4 + (size_t)img0 * 128;
    for (int i = t; i < 1024; i += 256) sx[i] = src[i];
    __syncthreads();
    float s_out = scl[4];
    int co = t;
    float acc[8][4];
#pragma unroll
    for (int im = 0; im < 8; im++)
#pragma unroll
        for (int p = 0; p < 4; p++) acc[im][p] = 0.f;
#pragma unroll
    for (int r = 0; r < 9; r++) {
        int ky = r / 3, kx = r % 3;
#pragma unroll 2
        for (int ci4 = 0; ci4 < 32; ci4++) {
            float4 wv = __ldg(&g_w5T4[(co * 9 + r) * 32 + ci4]);
#pragma unroll
            for (int im = 0; im < 8; im++) {
#pragma unroll
                for (int p = 0; p < 4; p++) {
                    int iy = (p >> 1) - 1 + ky;
                    int ix = (p & 1) - 1 + kx;
                    if (iy < 0 || iy > 1 || ix < 0 || ix > 1) continue;
                    float4 xv = sx[(im * 4 + (iy * 2 + ix)) * 32 + ci4];
                    FMA4(acc[im][p], xv, wv);
                }
            }
        }
    }
    float b = __ldg(b5c + co);
#pragma unroll
    for (int im = 0; im < 8; im++) {
        float mx = fmaxf(fmaxf(acc[im][0], acc[im][1]), fmaxf(acc[im][2], acc[im][3]));
        float y = __fadd_rn(mx, b);
        g_a5[(size_t)(img0 + im) * 256 + co] = qval_relu(y, s_out);
    }
}

// ---------------------------------------------------------------------------
// head: fc1 (256->512 qrelu) + fc2 (512->43 qid) + softmax. 8 imgs/block.
// ---------------------------------------------------------------------------
__global__ __launch_bounds__(256) void head_kernel(
    const float* __restrict__ bf1c, const float* __restrict__ bf2c,
    const float* __restrict__ scl, float* __restrict__ out, int B) {
    __shared__ float smh[2048 + 4096 + 344];
    float* a5s = smh;          // 8 x 256
    float* f1s = smh + 2048;   // 8 x 512
    float* lg = smh + 6144;    // 8 x 43
    int t = threadIdx.x;
    int img0 = blockIdx.x * 8;
    const float* src = g_a5 + (size_t)img0 * 256;
    for (int i = t; i < 2048; i += 256) a5s[i] = src[i];
    __syncthreads();

    // fc1 (k ascending)
    {
        const float4* a5s4 = (const float4*)a5s;  // [8][64]
        float s_out = scl[5];
#pragma unroll
        for (int rep = 0; rep < 2; rep++) {
            int n = t + rep * 256;
            float acc[8];
#pragma unroll
            for (int im = 0; im < 8; im++) acc[im] = 0.f;
#pragma unroll 4
            for (int k4 = 0; k4 < 64; k4++) {
                float4 wv = __ldg(&g_wf1q4[n * 64 + k4]);
#pragma unroll
                for (int im = 0; im < 8; im++) {
                    float4 xv = a5s4[im * 64 + k4];
                    FMA4(acc[im], xv, wv);
                }
            }
            float b = __ldg(bf1c + n);
#pragma unroll
            for (int im = 0; im < 8; im++) {
                float y = __fadd_rn(acc[im], b);
                f1s[im * 512 + n] = qval_relu(y, s_out);
            }
        }
    }
    __syncthreads();

    // fc2 + quant_identity
    {
        const float4* f1s4 = (const float4*)f1s;  // [8][128]
        float s_out = scl[6];
        if (t < 172) {
            int n = t >> 2, pair = t & 3;
            float a0 = 0.f, a1 = 0.f;
#pragma unroll 4
            for (int k4 = 0; k4 < 128; k4++) {
                float4 wv = __ldg(&g_wf2q4[n * 128 + k4]);
                float4 x0 = f1s4[(pair * 2) * 128 + k4];
                float4 x1 = f1s4[(pair * 2 + 1) * 128 + k4];
                FMA4(a0, x0, wv);
                FMA4(a1, x1, wv);
            }
            float b = __ldg(bf2c + n);
            lg[(pair * 2) * 43 + n] = qval_id(__fadd_rn(a0, b), s_out);
            lg[(pair * 2 + 1) * 43 + n] = qval_id(__fadd_rn(a1, b), s_out);
        }
    }
    __syncthreads();

    // softmax (43 classes, one warp per image)
    {
        int lane = t & 31, w = t >> 5;
        float v0 = lg[w * 43 + lane];
        float v1 = (lane < 11) ? lg[w * 43 + 32 + lane] : -INFINITY;
        float mx = fmaxf(v0, v1);
#pragma unroll
        for (int o = 16; o > 0; o >>= 1) mx = fmaxf(mx, __shfl_xor_sync(0xffffffffu, mx, o));
        float e0 = expf(v0 - mx);
        float e1 = (lane < 11) ? expf(v1 - mx) : 0.f;
        float sum = e0 + e1;
#pragma unroll
        for (int o = 16; o > 0; o >>= 1) sum += __shfl_xor_sync(0xffffffffu, sum, o);
        if ((img0 + w) < B) {
            out[(size_t)(img0 + w) * 43 + lane] = __fdiv_rn(e0, sum);
            if (lane < 11)
                out[(size_t)(img0 + w) * 43 + 32 + lane] = __fdiv_rn(e1, sum);
        }
    }
}

// ---------------------------------------------------------------------------
extern "C" void kernel_launch(void* const* d_in, const int* in_sizes, int n_in,
                              void* d_out, int out_size) {
    const float *x = 0, *w1 = 0, *b1 = 0, *w2 = 0, *b2 = 0, *w3 = 0, *b3 = 0;
    const float *w4 = 0, *b4 = 0, *w5 = 0, *b5 = 0, *wf1 = 0, *bf1 = 0;
    const float *wf2 = 0, *bf2 = 0, *scl = 0;
    int B = 2048;
    for (int i = 0; i < n_in; i++) {
        const float* p = (const float*)d_in[i];
        switch (in_sizes[i]) {
            case 432:    w1 = p;  break;
            case 16:     b1 = p;  break;
            case 4608:   w2 = p;  break;
            case 32:     b2 = p;  break;
            case 18432:  w3 = p;  break;
            case 64:     b3 = p;  break;
            case 73728:  w4 = p;  break;
            case 128:    b4 = p;  break;
            case 294912: w5 = p;  break;
            case 256:    b5 = p;  break;
            case 131072: wf1 = p; break;
            case 512:    bf1 = p; break;
            case 22016:  wf2 = p; break;
            case 43:     bf2 = p; break;
            case 7:      scl = p; break;
            default:     x = p; B = in_sizes[i] / 3072; break;
        }
    }
    float* out = (float*)d_out;

    quant_weights_kernel<<<7, 256>>>(w1, w2, w3, w4, w5, wf1, wf2);
    conv1_kernel<<<B, 256>>>(x, b1, scl);
    conv2_kernel<<<B / 2, 256>>>(b2, scl);
    conv3_kernel<<<B / 4, 256>>>(b3, scl);
    conv4_kernel<<<B / 8, 256>>>(b4, scl);
    conv5_kernel<<<B / 8, 256>>>(b5, scl);
    head_kernel<<<B / 8, 256>>>(bf1, bf2, scl, out, B);
}

// round 15
// speedup vs baseline: 2.6309x; 1.0779x over previous
#include <cuda_runtime.h>
#include <math.h>
#include <stdint.h>

// ---------------------------------------------------------------------------
// TSRNet 4-bit fake-quant CNN — per-layer kernels, reference-order fp32 FMA.
// R15: weight layouts transposed for lane-parallel consumers: conv5 weights
// [r][ci4][co] (lanes = co -> coalesced LDG.128), fc1/fc2 [k4][n]. Values and
// FMA chain orders bit-identical to R14 (rel_err 4.77e-8); addressing only.
// ---------------------------------------------------------------------------

#define BMAX 2048

__device__ float  g_w1T[16 * 27];            // [co][r][ci], ci=3
__device__ float4 g_w2T4[32 * 9 * 4];        // [co][r][ci4], CI=16
__device__ float4 g_w3T4[64 * 9 * 8];        // CI=32
__device__ float4 g_w4T4[128 * 9 * 16];      // CI=64
__device__ float4 g_w5T4[9 * 32 * 256];      // [r][ci4][co] (coalesced, lanes=co)
__device__ float4 g_wf1q4[64 * 512];         // [k4][n], K=256, N=512
__device__ float4 g_wf2q4[128 * 43];         // [k4][n], K=512, N=43

__device__ float4 g_a1[BMAX * 1024];  // [img][256 sp][16ci]/4
__device__ float4 g_a2[BMAX * 512];   // [img][64][32]/4
__device__ float4 g_a3[BMAX * 256];   // [img][16][64]/4
__device__ float4 g_a4[BMAX * 128];   // [img][4][128]/4
__device__ float  g_a5[BMAX * 256];   // [img][256]

__device__ __forceinline__ float qval_relu(float y, float s) {
    float u = __fdiv_rn(y, s);
    float k = rintf(u);
    k = fminf(fmaxf(k, 0.f), 15.f);
    return __fmul_rn(k, s);
}
__device__ __forceinline__ float qval_id(float y, float s) {
    float u = __fdiv_rn(y, s);
    float k = rintf(u);
    k = fminf(fmaxf(k, -8.f), 7.f);
    return __fmul_rn(k, s);
}

#define FMA4(acc, xv, wv)                        \
    do {                                         \
        acc = __fmaf_rn((xv).x, (wv).x, acc);    \
        acc = __fmaf_rn((xv).y, (wv).y, acc);    \
        acc = __fmaf_rn((xv).z, (wv).z, acc);    \
        acc = __fmaf_rn((xv).w, (wv).w, acc);    \
    } while (0)

// ---------------------------------------------------------------------------
// Weight quant (per-tensor symmetric, n=7) + layout transforms.
// mode 0: conv [co][r][ci];  mode 1: conv5 [r][ci4][co];  mode 2: fc [k4][n].
// ---------------------------------------------------------------------------
__global__ __launch_bounds__(256) void quant_weights_kernel(
    const float* w1, const float* w2, const float* w3, const float* w4,
    const float* w5, const float* wf1, const float* wf2) {
    __shared__ float red[256];
    __shared__ float s_scale;
    const float* src;
    float* dst;
    int n, ci_dim, mode, Kdim, Ndim;
    mode = 0; Kdim = 0; Ndim = 0; ci_dim = 0;
    switch (blockIdx.x) {
        case 0: src = w1;  dst = g_w1T;           n = 432;    ci_dim = 3;  break;
        case 1: src = w2;  dst = (float*)g_w2T4;  n = 4608;   ci_dim = 16; break;
        case 2: src = w3;  dst = (float*)g_w3T4;  n = 18432;  ci_dim = 32; break;
        case 3: src = w4;  dst = (float*)g_w4T4;  n = 73728;  ci_dim = 64; break;
        case 4: src = w5;  dst = (float*)g_w5T4;  n = 294912; mode = 1;    break;
        case 5: src = wf1; dst = (float*)g_wf1q4; n = 131072; mode = 2; Kdim = 256; Ndim = 512; break;
        default: src = wf2; dst = (float*)g_wf2q4; n = 22016; mode = 2; Kdim = 512; Ndim = 43;  break;
    }
    int t = threadIdx.x;
    float m = 0.f;
    for (int i = t; i < n; i += 256) m = fmaxf(m, fabsf(src[i]));
    red[t] = m;
    __syncthreads();
    for (int s = 128; s > 0; s >>= 1) {
        if (t < s) red[t] = fmaxf(red[t], red[t + s]);
        __syncthreads();
    }
    if (t == 0) s_scale = __fdiv_rn(red[0], 7.0f);
    __syncthreads();
    float sc = s_scale;
    for (int i = t; i < n; i += 256) {
        float wq = 0.f;
        if (sc > 0.f) {
            float q = rintf(__fdiv_rn(src[i], sc));
            q = fminf(fmaxf(q, -7.f), 7.f);
            wq = __fmul_rn(q, sc);
        }
        if (mode == 0) {
            int co = i / (ci_dim * 9);
            int rem = i % (ci_dim * 9);
            int ci = rem / 9;
            int r = rem % 9;
            dst[(co * 9 + r) * ci_dim + ci] = wq;
        } else if (mode == 1) {
            // w5: src [co=256][ci=128][r=9] -> [r][ci4][co] float4 over ci%4
            int co = i / 1152;
            int rem = i % 1152;
            int ci = rem / 9;
            int r = rem % 9;
            dst[(((r * 32 + (ci >> 2)) * 256 + co) << 2) + (ci & 3)] = wq;
        } else {
            // fc: src [n][k] -> [k4][n] float4 over k%4
            int nn = i / Kdim;
            int k = i % Kdim;
            dst[(((k >> 2) * Ndim + nn) << 2) + (k & 3)] = wq;
        }
    }
}

// ---------------------------------------------------------------------------
// conv1: 3->16, 32x32 -> pooled 16x16. One image per block (register conv).
// ---------------------------------------------------------------------------
__global__ __launch_bounds__(256) void conv1_kernel(
    const float* __restrict__ x, const float* __restrict__ b1c,
    const float* __restrict__ scl) {
    __shared__ float sxT[3072];  // [32][32][3]
    __shared__ float sw1[432];
    int t = threadIdx.x;
    int img = blockIdx.x;
    for (int i = t; i < 432; i += 256) sw1[i] = g_w1T[i];
    const float* xs = x + (size_t)img * 3072;
    for (int i = t; i < 3072; i += 256) {
        int ci = i >> 10, sp = i & 1023;
        sxT[sp * 3 + ci] = xs[i];
    }
    __syncthreads();
    float s0 = scl[0];
    int py = t >> 4, px = t & 15;
    float win[4][4][3];
#pragma unroll
    for (int wy = 0; wy < 4; wy++) {
        int iy = 2 * py - 1 + wy;
#pragma unroll
        for (int wx = 0; wx < 4; wx++) {
            int ix = 2 * px - 1 + wx;
            bool v = (iy >= 0 && iy < 32 && ix >= 0 && ix < 32);
#pragma unroll
            for (int ci = 0; ci < 3; ci++)
                win[wy][wx][ci] = v ? sxT[(iy * 32 + ix) * 3 + ci] : 0.f;
        }
    }
    float* o = (float*)(g_a1 + (size_t)img * 1024);
#pragma unroll 2
    for (int co = 0; co < 16; co++) {
        float a0 = 0.f, a1 = 0.f, a2 = 0.f, a3 = 0.f;
#pragma unroll
        for (int r = 0; r < 9; r++) {
            int ky = r / 3, kx = r % 3;
#pragma unroll
            for (int ci = 0; ci < 3; ci++) {
                float wv = sw1[co * 27 + r * 3 + ci];
                a0 = __fmaf_rn(win[ky][kx][ci], wv, a0);
                a1 = __fmaf_rn(win[ky][kx + 1][ci], wv, a1);
                a2 = __fmaf_rn(win[ky + 1][kx][ci], wv, a2);
                a3 = __fmaf_rn(win[ky + 1][kx + 1][ci], wv, a3);
            }
        }
        float mx = fmaxf(fmaxf(a0, a1), fmaxf(a2, a3));
        float y = __fadd_rn(mx, __ldg(b1c + co));
        o[(py * 16 + px) * 16 + co] = qval_relu(y, s0);
    }
}

// ---------------------------------------------------------------------------
// conv2: 16->32, 16x16 -> pooled 8x8. 2 images/block. SMEM row stride 5 f4.
// ---------------------------------------------------------------------------
__global__ __launch_bounds__(256, 2) void conv2_kernel(
    const float* __restrict__ b2c, const float* __restrict__ scl) {
    __shared__ float4 sx[2560];  // 2 img x 256 sp x 5 f4 = 40KB
    int t = threadIdx.x;
    int img0 = blockIdx.x * 2;
    const float4* src = g_a1 + (size_t)img0 * 1024;
    for (int i = t; i < 2048; i += 256) {
        int img = i >> 10, rem = i & 1023;
        int sp = rem >> 2, ci4 = rem & 3;
        sx[img * 1280 + sp * 5 + ci4] = src[i];
    }
    __syncthreads();
    float s_out = scl[1];
    int warp = t >> 5, lane = t & 31;
    int im = warp & 1;
    int h = (warp >> 1) & 1;
    int co0 = (warp >> 2) * 16;
    int sp = h * 32 + lane;
    int py = sp >> 3, px = sp & 7;
    int base = im * 1280;
    float acc[16][4];
#pragma unroll
    for (int c = 0; c < 16; c++)
#pragma unroll
        for (int p = 0; p < 4; p++) acc[c][p] = 0.f;
#pragma unroll
    for (int r = 0; r < 9; r++) {
        int ky = r / 3, kx = r % 3;
        int o[4];
        bool v[4];
#pragma unroll
        for (int p = 0; p < 4; p++) {
            int iy = 2 * py + (p >> 1) - 1 + ky;
            int ix = 2 * px + (p & 1) - 1 + kx;
            v[p] = ((unsigned)iy < 16u) && ((unsigned)ix < 16u);
            o[p] = base + (iy * 16 + ix) * 5;
        }
#pragma unroll 2
        for (int ci4 = 0; ci4 < 4; ci4++) {
            float4 xv[4];
#pragma unroll
            for (int p = 0; p < 4; p++)
                xv[p] = v[p] ? sx[o[p] + ci4] : make_float4(0.f, 0.f, 0.f, 0.f);
#pragma unroll
            for (int ch = 0; ch < 2; ch++) {
#pragma unroll
                for (int c = 0; c < 8; c++) {
                    int cc = ch * 8 + c;
                    float4 wv = __ldg(&g_w2T4[((co0 + cc) * 9 + r) * 4 + ci4]);
#pragma unroll
                    for (int p = 0; p < 4; p++) FMA4(acc[cc][p], xv[p], wv);
                }
            }
        }
    }
    float* o2 = (float*)(g_a2 + (size_t)(img0 + im) * 512);
#pragma unroll
    for (int c = 0; c < 16; c++) {
        int co = co0 + c;
        float mx = fmaxf(fmaxf(acc[c][0], acc[c][1]), fmaxf(acc[c][2], acc[c][3]));
        float y = __fadd_rn(mx, __ldg(b2c + co));
        o2[sp * 32 + co] = qval_relu(y, s_out);
    }
}

// ---------------------------------------------------------------------------
// conv3: 32->64, 8x8 -> pooled 4x4. 4 images/block. SMEM row stride 9 f4.
// ---------------------------------------------------------------------------
__global__ __launch_bounds__(256, 2) void conv3_kernel(
    const float* __restrict__ b3c, const float* __restrict__ scl) {
    __shared__ float4 sx[2304];  // 4 img x 64 sp x 9 f4 = 36KB
    int t = threadIdx.x;
    int img0 = blockIdx.x * 4;
    const float4* src = g_a2 + (size_t)img0 * 512;
    for (int i = t; i < 2048; i += 256) {
        int img = i >> 9, rem = i & 511;
        int sp = rem >> 3, ci4 = rem & 7;
        sx[img * 576 + sp * 9 + ci4] = src[i];
    }
    __syncthreads();
    float s_out = scl[2];
    int warp = t >> 5, lane = t & 31;
    int p2 = warp & 1;
    int co0 = (warp >> 1) * 16;
    int im = lane >> 4, sp = lane & 15;
    int py = sp >> 2, px = sp & 3;
    int base = (p2 * 2 + im) * 576;
    float acc[16][4];
#pragma unroll
    for (int c = 0; c < 16; c++)
#pragma unroll
        for (int p = 0; p < 4; p++) acc[c][p] = 0.f;
#pragma unroll
    for (int r = 0; r < 9; r++) {
        int ky = r / 3, kx = r % 3;
        int o[4];
        bool v[4];
#pragma unroll
        for (int p = 0; p < 4; p++) {
            int iy = 2 * py + (p >> 1) - 1 + ky;
            int ix = 2 * px + (p & 1) - 1 + kx;
            v[p] = ((unsigned)iy < 8u) && ((unsigned)ix < 8u);
            o[p] = base + (iy * 8 + ix) * 9;
        }
#pragma unroll 2
        for (int ci4 = 0; ci4 < 8; ci4++) {
            float4 xv[4];
#pragma unroll
            for (int p = 0; p < 4; p++)
                xv[p] = v[p] ? sx[o[p] + ci4] : make_float4(0.f, 0.f, 0.f, 0.f);
#pragma unroll
            for (int ch = 0; ch < 2; ch++) {
#pragma unroll
                for (int c = 0; c < 8; c++) {
                    int cc = ch * 8 + c;
                    float4 wv = __ldg(&g_w3T4[((co0 + cc) * 9 + r) * 8 + ci4]);
#pragma unroll
                    for (int p = 0; p < 4; p++) FMA4(acc[cc][p], xv[p], wv);
                }
            }
        }
    }
    float* o3 = (float*)(g_a3 + (size_t)(img0 + p2 * 2 + im) * 256);
#pragma unroll
    for (int c = 0; c < 16; c++) {
        int co = co0 + c;
        float mx = fmaxf(fmaxf(acc[c][0], acc[c][1]), fmaxf(acc[c][2], acc[c][3]));
        float y = __fadd_rn(mx, __ldg(b3c + co));
        o3[sp * 64 + co] = qval_relu(y, s_out);
    }
}

// ---------------------------------------------------------------------------
// conv4: 64->128, 4x4 -> pooled 2x2. 8 images/block. SMEM row stride 17 f4.
// ---------------------------------------------------------------------------
__global__ __launch_bounds__(256, 2) void conv4_kernel(
    const float* __restrict__ b4c, const float* __restrict__ scl) {
    __shared__ float4 sx[2176];  // 8 img x 16 sp x 17 f4 = 34KB
    int t = threadIdx.x;
    int img0 = blockIdx.x * 8;
    const float4* src = g_a3 + (size_t)img0 * 256;
    for (int i = t; i < 2048; i += 256) {
        int img = i >> 8, rem = i & 255;
        int sp = rem >> 4, ci4 = rem & 15;
        sx[img * 272 + sp * 17 + ci4] = src[i];
    }
    __syncthreads();
    float s_out = scl[3];
    int warp = t >> 5, lane = t & 31;
    int co0 = warp * 16;
    int im = lane >> 2, q = lane & 3;
    int qy = q >> 1, qx = q & 1;
    int base = im * 272;
    float acc[16][4];
#pragma unroll
    for (int c = 0; c < 16; c++)
#pragma unroll
        for (int p = 0; p < 4; p++) acc[c][p] = 0.f;
#pragma unroll
    for (int r = 0; r < 9; r++) {
        int ky = r / 3, kx = r % 3;
        int o[4];
        bool v[4];
#pragma unroll
        for (int p = 0; p < 4; p++) {
            int iy = 2 * qy + (p >> 1) - 1 + ky;
            int ix = 2 * qx + (p & 1) - 1 + kx;
            v[p] = ((unsigned)iy < 4u) && ((unsigned)ix < 4u);
            o[p] = base + (iy * 4 + ix) * 17;
        }
#pragma unroll 1
        for (int ci4 = 0; ci4 < 16; ci4++) {
            float4 xv[4];
#pragma unroll
            for (int p = 0; p < 4; p++)
                xv[p] = v[p] ? sx[o[p] + ci4] : make_float4(0.f, 0.f, 0.f, 0.f);
#pragma unroll
            for (int ch = 0; ch < 2; ch++) {
#pragma unroll
                for (int c = 0; c < 8; c++) {
                    int cc = ch * 8 + c;
                    float4 wv = __ldg(&g_w4T4[((co0 + cc) * 9 + r) * 16 + ci4]);
#pragma unroll
                    for (int p = 0; p < 4; p++) FMA4(acc[cc][p], xv[p], wv);
                }
            }
        }
    }
    float* o4 = (float*)(g_a4 + (size_t)(img0 + im) * 128);
#pragma unroll
    for (int c = 0; c < 16; c++) {
        int co = co0 + c;
        float mx = fmaxf(fmaxf(acc[c][0], acc[c][1]), fmaxf(acc[c][2], acc[c][3]));
        float y = __fadd_rn(mx, __ldg(b4c + co));
        o4[q * 128 + co] = qval_relu(y, s_out);
    }
}

// ---------------------------------------------------------------------------
// conv5: 128->256, 2x2 -> pooled 1x1. 8 images/block; lanes = co; weight
// loads now COALESCED ([r][ci4][co] layout: adjacent lanes adjacent 16B).
// ---------------------------------------------------------------------------
__global__ __launch_bounds__(256) void conv5_kernel(
    const float* __restrict__ b5c, const float* __restrict__ scl) {
    __shared__ float4 sx[1024];  // 8 img x 128 f4
    int t = threadIdx.x;
    int img0 = blockIdx.x * 8;
    const float4* src = g_a4 + (size_t)img0 * 128;
    for (int i = t; i < 1024; i += 256) sx[i] = src[i];
    __syncthreads();
    float s_out = scl[4];
    int co = t;
    float acc[8][4];
#pragma unroll
    for (int im = 0; im < 8; im++)
#pragma unroll
        for (int p = 0; p < 4; p++) acc[im][p] = 0.f;
#pragma unroll
    for (int r = 0; r < 9; r++) {
        int ky = r / 3, kx = r % 3;
#pragma unroll 2
        for (int ci4 = 0; ci4 < 32; ci4++) {
            float4 wv = __ldg(&g_w5T4[(r * 32 + ci4) * 256 + co]);
#pragma unroll
            for (int im = 0; im < 8; im++) {
#pragma unroll
                for (int p = 0; p < 4; p++) {
                    int iy = (p >> 1) - 1 + ky;
                    int ix = (p & 1) - 1 + kx;
                    if (iy < 0 || iy > 1 || ix < 0 || ix > 1) continue;
                    float4 xv = sx[(im * 4 + (iy * 2 + ix)) * 32 + ci4];
                    FMA4(acc[im][p], xv, wv);
                }
            }
        }
    }
    float b = __ldg(b5c + co);
#pragma unroll
    for (int im = 0; im < 8; im++) {
        float mx = fmaxf(fmaxf(acc[im][0], acc[im][1]), fmaxf(acc[im][2], acc[im][3]));
        float y = __fadd_rn(mx, b);
        g_a5[(size_t)(img0 + im) * 256 + co] = qval_relu(y, s_out);
    }
}

// ---------------------------------------------------------------------------
// head: fc1 (256->512 qrelu) + fc2 (512->43 qid) + softmax. 8 imgs/block.
// fc weights in [k4][n] layout -> coalesced over lanes (n).
// ---------------------------------------------------------------------------
__global__ __launch_bounds__(256) void head_kernel(
    const float* __restrict__ bf1c, const float* __restrict__ bf2c,
    const float* __restrict__ scl, float* __restrict__ out, int B) {
    __shared__ float smh[2048 + 4096 + 344];
    float* a5s = smh;          // 8 x 256
    float* f1s = smh + 2048;   // 8 x 512
    float* lg = smh + 6144;    // 8 x 43
    int t = threadIdx.x;
    int img0 = blockIdx.x * 8;
    const float* src = g_a5 + (size_t)img0 * 256;
    for (int i = t; i < 2048; i += 256) a5s[i] = src[i];
    __syncthreads();

    // fc1 (k ascending)
    {
        const float4* a5s4 = (const float4*)a5s;  // [8][64]
        float s_out = scl[5];
#pragma unroll
        for (int rep = 0; rep < 2; rep++) {
            int n = t + rep * 256;
            float acc[8];
#pragma unroll
            for (int im = 0; im < 8; im++) acc[im] = 0.f;
#pragma unroll 4
            for (int k4 = 0; k4 < 64; k4++) {
                float4 wv = __ldg(&g_wf1q4[k4 * 512 + n]);
#pragma unroll
                for (int im = 0; im < 8; im++) {
                    float4 xv = a5s4[im * 64 + k4];
                    FMA4(acc[im], xv, wv);
                }
            }
            float b = __ldg(bf1c + n);
#pragma unroll
            for (int im = 0; im < 8; im++) {
                float y = __fadd_rn(acc[im], b);
                f1s[im * 512 + n] = qval_relu(y, s_out);
            }
        }
    }
    __syncthreads();

    // fc2 + quant_identity
    {
        const float4* f1s4 = (const float4*)f1s;  // [8][128]
        float s_out = scl[6];
        if (t < 172) {
            int n = t >> 2, pair = t & 3;
            float a0 = 0.f, a1 = 0.f;
#pragma unroll 4
            for (int k4 = 0; k4 < 128; k4++) {
                float4 wv = __ldg(&g_wf2q4[k4 * 43 + n]);
                float4 x0 = f1s4[(pair * 2) * 128 + k4];
                float4 x1 = f1s4[(pair * 2 + 1) * 128 + k4];
                FMA4(a0, x0, wv);
                FMA4(a1, x1, wv);
            }
            float b = __ldg(bf2c + n);
            lg[(pair * 2) * 43 + n] = qval_id(__fadd_rn(a0, b), s_out);
            lg[(pair * 2 + 1) * 43 + n] = qval_id(__fadd_rn(a1, b), s_out);
        }
    }
    __syncthreads();

    // softmax (43 classes, one warp per image)
    {
        int lane = t & 31, w = t >> 5;
        float v0 = lg[w * 43 + lane];
        float v1 = (lane < 11) ? lg[w * 43 + 32 + lane] : -INFINITY;
        float mx = fmaxf(v0, v1);
#pragma unroll
        for (int o = 16; o > 0; o >>= 1) mx = fmaxf(mx, __shfl_xor_sync(0xffffffffu, mx, o));
        float e0 = expf(v0 - mx);
        float e1 = (lane < 11) ? expf(v1 - mx) : 0.f;
        float sum = e0 + e1;
#pragma unroll
        for (int o = 16; o > 0; o >>= 1) sum += __shfl_xor_sync(0xffffffffu, sum, o);
        if ((img0 + w) < B) {
            out[(size_t)(img0 + w) * 43 + lane] = __fdiv_rn(e0, sum);
            if (lane < 11)
                out[(size_t)(img0 + w) * 43 + 32 + lane] = __fdiv_rn(e1, sum);
        }
    }
}

// ---------------------------------------------------------------------------
extern "C" void kernel_launch(void* const* d_in, const int* in_sizes, int n_in,
                              void* d_out, int out_size) {
    const float *x = 0, *w1 = 0, *b1 = 0, *w2 = 0, *b2 = 0, *w3 = 0, *b3 = 0;
    const float *w4 = 0, *b4 = 0, *w5 = 0, *b5 = 0, *wf1 = 0, *bf1 = 0;
    const float *wf2 = 0, *bf2 = 0, *scl = 0;
    int B = 2048;
    for (int i = 0; i < n_in; i++) {
        const float* p = (const float*)d_in[i];
        switch (in_sizes[i]) {
            case 432:    w1 = p;  break;
            case 16:     b1 = p;  break;
            case 4608:   w2 = p;  break;
            case 32:     b2 = p;  break;
            case 18432:  w3 = p;  break;
            case 64:     b3 = p;  break;
            case 73728:  w4 = p;  break;
            case 128:    b4 = p;  break;
            case 294912: w5 = p;  break;
            case 256:    b5 = p;  break;
            case 131072: wf1 = p; break;
            case 512:    bf1 = p; break;
            case 22016:  wf2 = p; break;
            case 43:     bf2 = p; break;
            case 7:      scl = p; break;
            default:     x = p; B = in_sizes[i] / 3072; break;
        }
    }
    float* out = (float*)d_out;

    quant_weights_kernel<<<7, 256>>>(w1, w2, w3, w4, w5, wf1, wf2);
    conv1_kernel<<<B, 256>>>(x, b1, scl);
    conv2_kernel<<<B / 2, 256>>>(b2, scl);
    conv3_kernel<<<B / 4, 256>>>(b3, scl);
    conv4_kernel<<<B / 8, 256>>>(b4, scl);
    conv5_kernel<<<B / 8, 256>>>(b5, scl);
    head_kernel<<<B / 8, 256>>>(bf1, bf2, scl, out, B);
}

// round 16
// speedup vs baseline: 2.6360x; 1.0019x over previous
#include <cuda_runtime.h>
#include <math.h>
#include <stdint.h>

// ---------------------------------------------------------------------------
// TSRNet 4-bit fake-quant CNN — per-layer kernels, reference-order fp32 FMA.
// R16: conv2/3/4 use packed f32x2 FMA (SASS FFMA2, PTX fma.rn.f32x2): two
// output channels per instruction. Weights stored pair-interleaved
// [co/2][r][ci4][e][2] so LDG.128 returns two pre-packed (c0,c1) ulls.
// Each accumulator's chain keeps the exact R8 order -> bit-identical.
// ---------------------------------------------------------------------------

#define BMAX 2048

__device__ float  g_w1T[16 * 27];      // [co][r][ci], ci=3
__device__ float4 g_w2p4[1152];        // conv2 pair-interleaved (4608 floats)
__device__ float4 g_w3p4[4608];        // conv3 (18432 floats)
__device__ float4 g_w4p4[18432];       // conv4 (73728 floats)
__device__ float4 g_w5T4[9 * 32 * 256];// [r][ci4][co] (coalesced, lanes=co)
__device__ float4 g_wf1q4[64 * 512];   // [k4][n], K=256, N=512
__device__ float4 g_wf2q4[128 * 43];   // [k4][n], K=512, N=43

__device__ float4 g_a1[BMAX * 1024];  // [img][256 sp][16ci]/4
__device__ float4 g_a2[BMAX * 512];   // [img][64][32]/4
__device__ float4 g_a3[BMAX * 256];   // [img][16][64]/4
__device__ float4 g_a4[BMAX * 128];   // [img][4][128]/4
__device__ float  g_a5[BMAX * 256];   // [img][256]

typedef unsigned long long ull;

__device__ __forceinline__ void ffma2(ull& acc, ull a, ull b) {
    asm("fma.rn.f32x2 %0, %1, %2, %0;" : "+l"(acc) : "l"(a), "l"(b));
}
__device__ __forceinline__ ull pk2(float lo, float hi) {
    ull r;
    asm("mov.b64 %0, {%1, %2};" : "=l"(r) : "f"(lo), "f"(hi));
    return r;
}
__device__ __forceinline__ void upk2(ull v, float& lo, float& hi) {
    asm("mov.b64 {%0, %1}, %2;" : "=f"(lo), "=f"(hi) : "l"(v));
}

__device__ __forceinline__ float qval_relu(float y, float s) {
    float u = __fdiv_rn(y, s);
    float k = rintf(u);
    k = fminf(fmaxf(k, 0.f), 15.f);
    return __fmul_rn(k, s);
}
__device__ __forceinline__ float qval_id(float y, float s) {
    float u = __fdiv_rn(y, s);
    float k = rintf(u);
    k = fminf(fmaxf(k, -8.f), 7.f);
    return __fmul_rn(k, s);
}

#define FMA4(acc, xv, wv)                        \
    do {                                         \
        acc = __fmaf_rn((xv).x, (wv).x, acc);    \
        acc = __fmaf_rn((xv).y, (wv).y, acc);    \
        acc = __fmaf_rn((xv).z, (wv).z, acc);    \
        acc = __fmaf_rn((xv).w, (wv).w, acc);    \
    } while (0)

// ---------------------------------------------------------------------------
// Weight quant (per-tensor symmetric, n=7) + layout transforms.
// mode 0: conv1 [co][r][ci];  mode 1: conv5 [r][ci4][co];  mode 2: fc [k4][n];
// mode 3: conv pair-interleaved [co/2][r][ci4][e][2].
// ---------------------------------------------------------------------------
__global__ __launch_bounds__(256) void quant_weights_kernel(
    const float* w1, const float* w2, const float* w3, const float* w4,
    const float* w5, const float* wf1, const float* wf2) {
    __shared__ float red[256];
    __shared__ float s_scale;
    const float* src;
    float* dst;
    int n, ci_dim, mode, Kdim, Ndim;
    mode = 0; Kdim = 0; Ndim = 0; ci_dim = 0;
    switch (blockIdx.x) {
        case 0: src = w1;  dst = g_w1T;           n = 432;    ci_dim = 3;  break;
        case 1: src = w2;  dst = (float*)g_w2p4;  n = 4608;   ci_dim = 16; mode = 3; break;
        case 2: src = w3;  dst = (float*)g_w3p4;  n = 18432;  ci_dim = 32; mode = 3; break;
        case 3: src = w4;  dst = (float*)g_w4p4;  n = 73728;  ci_dim = 64; mode = 3; break;
        case 4: src = w5;  dst = (float*)g_w5T4;  n = 294912; mode = 1;    break;
        case 5: src = wf1; dst = (float*)g_wf1q4; n = 131072; mode = 2; Kdim = 256; Ndim = 512; break;
        default: src = wf2; dst = (float*)g_wf2q4; n = 22016; mode = 2; Kdim = 512; Ndim = 43;  break;
    }
    int t = threadIdx.x;
    float m = 0.f;
    for (int i = t; i < n; i += 256) m = fmaxf(m, fabsf(src[i]));
    red[t] = m;
    __syncthreads();
    for (int s = 128; s > 0; s >>= 1) {
        if (t < s) red[t] = fmaxf(red[t], red[t + s]);
        __syncthreads();
    }
    if (t == 0) s_scale = __fdiv_rn(red[0], 7.0f);
    __syncthreads();
    float sc = s_scale;
    for (int i = t; i < n; i += 256) {
        float wq = 0.f;
        if (sc > 0.f) {
            float q = rintf(__fdiv_rn(src[i], sc));
            q = fminf(fmaxf(q, -7.f), 7.f);
            wq = __fmul_rn(q, sc);
        }
        if (mode == 0) {
            int co = i / (ci_dim * 9);
            int rem = i % (ci_dim * 9);
            int ci = rem / 9;
            int r = rem % 9;
            dst[(co * 9 + r) * ci_dim + ci] = wq;
        } else if (mode == 1) {
            int co = i / 1152;
            int rem = i % 1152;
            int ci = rem / 9;
            int r = rem % 9;
            dst[(((r * 32 + (ci >> 2)) * 256 + co) << 2) + (ci & 3)] = wq;
        } else if (mode == 2) {
            int nn = i / Kdim;
            int k = i % Kdim;
            dst[(((k >> 2) * Ndim + nn) << 2) + (k & 3)] = wq;
        } else {
            // mode 3: [co/2][r][ci4][e(=ci&3)][co&1]
            int co = i / (ci_dim * 9);
            int rem = i % (ci_dim * 9);
            int ci = rem / 9;
            int r = rem % 9;
            int idx = (((((co >> 1) * 9 + r) * (ci_dim >> 2) + (ci >> 2)) * 4 + (ci & 3)) << 1) + (co & 1);
            dst[idx] = wq;
        }
    }
}

// ---------------------------------------------------------------------------
// conv1: 3->16, 32x32 -> pooled 16x16. One image per block (register conv).
// ---------------------------------------------------------------------------
__global__ __launch_bounds__(256) void conv1_kernel(
    const float* __restrict__ x, const float* __restrict__ b1c,
    const float* __restrict__ scl) {
    __shared__ float sxT[3072];  // [32][32][3]
    __shared__ float sw1[432];
    int t = threadIdx.x;
    int img = blockIdx.x;
    for (int i = t; i < 432; i += 256) sw1[i] = g_w1T[i];
    const float* xs = x + (size_t)img * 3072;
    for (int i = t; i < 3072; i += 256) {
        int ci = i >> 10, sp = i & 1023;
        sxT[sp * 3 + ci] = xs[i];
    }
    __syncthreads();
    float s0 = scl[0];
    int py = t >> 4, px = t & 15;
    float win[4][4][3];
#pragma unroll
    for (int wy = 0; wy < 4; wy++) {
        int iy = 2 * py - 1 + wy;
#pragma unroll
        for (int wx = 0; wx < 4; wx++) {
            int ix = 2 * px - 1 + wx;
            bool v = (iy >= 0 && iy < 32 && ix >= 0 && ix < 32);
#pragma unroll
            for (int ci = 0; ci < 3; ci++)
                win[wy][wx][ci] = v ? sxT[(iy * 32 + ix) * 3 + ci] : 0.f;
        }
    }
    float* o = (float*)(g_a1 + (size_t)img * 1024);
#pragma unroll 2
    for (int co = 0; co < 16; co++) {
        float a0 = 0.f, a1 = 0.f, a2 = 0.f, a3 = 0.f;
#pragma unroll
        for (int r = 0; r < 9; r++) {
            int ky = r / 3, kx = r % 3;
#pragma unroll
            for (int ci = 0; ci < 3; ci++) {
                float wv = sw1[co * 27 + r * 3 + ci];
                a0 = __fmaf_rn(win[ky][kx][ci], wv, a0);
                a1 = __fmaf_rn(win[ky][kx + 1][ci], wv, a1);
                a2 = __fmaf_rn(win[ky + 1][kx][ci], wv, a2);
                a3 = __fmaf_rn(win[ky + 1][kx + 1][ci], wv, a3);
            }
        }
        float mx = fmaxf(fmaxf(a0, a1), fmaxf(a2, a3));
        float y = __fadd_rn(mx, __ldg(b1c + co));
        o[(py * 16 + px) * 16 + co] = qval_relu(y, s0);
    }
}

// ---------------------------------------------------------------------------
// Shared FFMA2 conv body for conv2/3/4: warp handles 16 co (8 pairs),
// lanes span (img x pooled sp), SMEM tile with odd f4 row stride.
// ---------------------------------------------------------------------------
#define CONV_FFMA2_BODY(CI4, WPAIRS, UNROLL_N)                                \
    ull acc2[8][4];                                                           \
    _Pragma("unroll") for (int c = 0; c < 8; c++)                             \
        _Pragma("unroll") for (int p = 0; p < 4; p++) acc2[c][p] = 0ull;      \
    _Pragma("unroll") for (int r = 0; r < 9; r++) {                           \
        int ky = r / 3, kx = r % 3;                                           \
        int o[4];                                                             \
        bool v[4];                                                            \
        _Pragma("unroll") for (int p = 0; p < 4; p++) {                       \
            int iy = 2 * py + (p >> 1) - 1 + ky;                              \
            int ix = 2 * px + (p & 1) - 1 + kx;                               \
            v[p] = ((unsigned)iy < (unsigned)H) && ((unsigned)ix < (unsigned)H); \
            o[p] = base + (iy * H + ix) * STR;                                \
        }                                                                     \
        _Pragma(UNROLL_N) for (int ci4 = 0; ci4 < CI4; ci4++) {               \
            ull xd[4][4];                                                     \
            _Pragma("unroll") for (int p = 0; p < 4; p++) {                   \
                float4 xv = v[p] ? sx[o[p] + ci4] : make_float4(0.f, 0.f, 0.f, 0.f); \
                xd[p][0] = pk2(xv.x, xv.x);                                   \
                xd[p][1] = pk2(xv.y, xv.y);                                   \
                xd[p][2] = pk2(xv.z, xv.z);                                   \
                xd[p][3] = pk2(xv.w, xv.w);                                   \
            }                                                                 \
            _Pragma("unroll") for (int c = 0; c < 8; c++) {                   \
                int wb = (((pr0 + c) * 9 + r) * CI4 + ci4) * 2;               \
                ulonglong2 wA = __ldg(&WPAIRS[wb]);                           \
                ulonglong2 wB = __ldg(&WPAIRS[wb + 1]);                       \
                _Pragma("unroll") for (int p = 0; p < 4; p++) {               \
                    ffma2(acc2[c][p], xd[p][0], wA.x);                        \
                    ffma2(acc2[c][p], xd[p][1], wA.y);                        \
                    ffma2(acc2[c][p], xd[p][2], wB.x);                        \
                    ffma2(acc2[c][p], xd[p][3], wB.y);                        \
                }                                                             \
            }                                                                 \
        }                                                                     \
    }

// ---------------------------------------------------------------------------
// conv2: 16->32, 16x16 -> pooled 8x8. 2 images/block. Row stride 5 f4.
// ---------------------------------------------------------------------------
__global__ __launch_bounds__(256, 2) void conv2_kernel(
    const float* __restrict__ b2c, const float* __restrict__ scl) {
    __shared__ float4 sx[2560];  // 2 img x 256 sp x 5 f4
    int t = threadIdx.x;
    int img0 = blockIdx.x * 2;
    const float4* src = g_a1 + (size_t)img0 * 1024;
    for (int i = t; i < 2048; i += 256) {
        int img = i >> 10, rem = i & 1023;
        int sp = rem >> 2, ci4 = rem & 3;
        sx[img * 1280 + sp * 5 + ci4] = src[i];
    }
    __syncthreads();
    float s_out = scl[1];
    int warp = t >> 5, lane = t & 31;
    int im = warp & 1;
    int h = (warp >> 1) & 1;
    int co0 = (warp >> 2) * 16;
    int pr0 = co0 >> 1;
    int sp = h * 32 + lane;
    int py = sp >> 3, px = sp & 7;
    int base = im * 1280;
    const int H = 16, STR = 5;
    const ulonglong2* wp2 = (const ulonglong2*)g_w2p4;
    CONV_FFMA2_BODY(4, wp2, "unroll 2")
    float* o2 = (float*)(g_a2 + (size_t)(img0 + im) * 512);
#pragma unroll
    for (int c = 0; c < 8; c++) {
        float lo[4], hi[4];
#pragma unroll
        for (int p = 0; p < 4; p++) upk2(acc2[c][p], lo[p], hi[p]);
        int co = co0 + 2 * c;
        float mxl = fmaxf(fmaxf(lo[0], lo[1]), fmaxf(lo[2], lo[3]));
        float mxh = fmaxf(fmaxf(hi[0], hi[1]), fmaxf(hi[2], hi[3]));
        o2[sp * 32 + co] = qval_relu(__fadd_rn(mxl, __ldg(b2c + co)), s_out);
        o2[sp * 32 + co + 1] = qval_relu(__fadd_rn(mxh, __ldg(b2c + co + 1)), s_out);
    }
}

// ---------------------------------------------------------------------------
// conv3: 32->64, 8x8 -> pooled 4x4. 4 images/block. Row stride 9 f4.
// ---------------------------------------------------------------------------
__global__ __launch_bounds__(256, 2) void conv3_kernel(
    const float* __restrict__ b3c, const float* __restrict__ scl) {
    __shared__ float4 sx[2304];  // 4 img x 64 sp x 9 f4
    int t = threadIdx.x;
    int img0 = blockIdx.x * 4;
    const float4* src = g_a2 + (size_t)img0 * 512;
    for (int i = t; i < 2048; i += 256) {
        int img = i >> 9, rem = i & 511;
        int sp = rem >> 3, ci4 = rem & 7;
        sx[img * 576 + sp * 9 + ci4] = src[i];
    }
    __syncthreads();
    float s_out = scl[2];
    int warp = t >> 5, lane = t & 31;
    int p2 = warp & 1;
    int co0 = (warp >> 1) * 16;
    int pr0 = co0 >> 1;
    int im = lane >> 4, sp = lane & 15;
    int py = sp >> 2, px = sp & 3;
    int base = (p2 * 2 + im) * 576;
    const int H = 8, STR = 9;
    const ulonglong2* wp3 = (const ulonglong2*)g_w3p4;
    CONV_FFMA2_BODY(8, wp3, "unroll 2")
    float* o3 = (float*)(g_a3 + (size_t)(img0 + p2 * 2 + im) * 256);
#pragma unroll
    for (int c = 0; c < 8; c++) {
        float lo[4], hi[4];
#pragma unroll
        for (int p = 0; p < 4; p++) upk2(acc2[c][p], lo[p], hi[p]);
        int co = co0 + 2 * c;
        float mxl = fmaxf(fmaxf(lo[0], lo[1]), fmaxf(lo[2], lo[3]));
        float mxh = fmaxf(fmaxf(hi[0], hi[1]), fmaxf(hi[2], hi[3]));
        o3[sp * 64 + co] = qval_relu(__fadd_rn(mxl, __ldg(b3c + co)), s_out);
        o3[sp * 64 + co + 1] = qval_relu(__fadd_rn(mxh, __ldg(b3c + co + 1)), s_out);
    }
}

// ---------------------------------------------------------------------------
// conv4: 64->128, 4x4 -> pooled 2x2. 8 images/block. Row stride 17 f4.
// ---------------------------------------------------------------------------
__global__ __launch_bounds__(256, 2) void conv4_kernel(
    const float* __restrict__ b4c, const float* __restrict__ scl) {
    __shared__ float4 sx[2176];  // 8 img x 16 sp x 17 f4
    int t = threadIdx.x;
    int img0 = blockIdx.x * 8;
    const float4* src = g_a3 + (size_t)img0 * 256;
    for (int i = t; i < 2048; i += 256) {
        int img = i >> 8, rem = i & 255;
        int sp = rem >> 4, ci4 = rem & 15;
        sx[img * 272 + sp * 17 + ci4] = src[i];
    }
    __syncthreads();
    float s_out = scl[3];
    int warp = t >> 5, lane = t & 31;
    int co0 = warp * 16;
    int pr0 = co0 >> 1;
    int im = lane >> 2, q = lane & 3;
    int py = q >> 1, px = q & 1;  // pooled coords
    int base = im * 272;
    const int H = 4, STR = 17;
    const ulonglong2* wp4 = (const ulonglong2*)g_w4p4;
    CONV_FFMA2_BODY(16, wp4, "unroll 1")
    float* o4 = (float*)(g_a4 + (size_t)(img0 + im) * 128);
#pragma unroll
    for (int c = 0; c < 8; c++) {
        float lo[4], hi[4];
#pragma unroll
        for (int p = 0; p < 4; p++) upk2(acc2[c][p], lo[p], hi[p]);
        int co = co0 + 2 * c;
        float mxl = fmaxf(fmaxf(lo[0], lo[1]), fmaxf(lo[2], lo[3]));
        float mxh = fmaxf(fmaxf(hi[0], hi[1]), fmaxf(hi[2], hi[3]));
        o4[q * 128 + co] = qval_relu(__fadd_rn(mxl, __ldg(b4c + co)), s_out);
        o4[q * 128 + co + 1] = qval_relu(__fadd_rn(mxh, __ldg(b4c + co + 1)), s_out);
    }
}

// ---------------------------------------------------------------------------
// conv5: 128->256, 2x2 -> pooled 1x1. 8 images/block; lanes = co; coalesced
// weights [r][ci4][co].
// ---------------------------------------------------------------------------
__global__ __launch_bounds__(256) void conv5_kernel(
    const float* __restrict__ b5c, const float* __restrict__ scl) {
    __shared__ float4 sx[1024];  // 8 img x 128 f4
    int t = threadIdx.x;
    int img0 = blockIdx.x * 8;
    const float4* src = g_a4 + (size_t)img0 * 128;
    for (int i = t; i < 1024; i += 256) sx[i] = src[i];
    __syncthreads();
    float s_out = scl[4];
    int co = t;
    float acc[8][4];
#pragma unroll
    for (int im = 0; im < 8; im++)
#pragma unroll
        for (int p = 0; p < 4; p++) acc[im][p] = 0.f;
#pragma unroll
    for (int r = 0; r < 9; r++) {
        int ky = r / 3, kx = r % 3;
#pragma unroll 2
        for (int ci4 = 0; ci4 < 32; ci4++) {
            float4 wv = __ldg(&g_w5T4[(r * 32 + ci4) * 256 + co]);
#pragma unroll
            for (int im = 0; im < 8; im++) {
#pragma unroll
                for (int p = 0; p < 4; p++) {
                    int iy = (p >> 1) - 1 + ky;
                    int ix = (p & 1) - 1 + kx;
                    if (iy < 0 || iy > 1 || ix < 0 || ix > 1) continue;
                    float4 xv = sx[(im * 4 + (iy * 2 + ix)) * 32 + ci4];
                    FMA4(acc[im][p], xv, wv);
                }
            }
        }
    }
    float b = __ldg(b5c + co);
#pragma unroll
    for (int im = 0; im < 8; im++) {
        float mx = fmaxf(fmaxf(acc[im][0], acc[im][1]), fmaxf(acc[im][2], acc[im][3]));
        float y = __fadd_rn(mx, b);
        g_a5[(size_t)(img0 + im) * 256 + co] = qval_relu(y, s_out);
    }
}

// ---------------------------------------------------------------------------
// head: fc1 (256->512 qrelu) + fc2 (512->43 qid) + softmax. 8 imgs/block.
// ---------------------------------------------------------------------------
__global__ __launch_bounds__(256) void head_kernel(
    const float* __restrict__ bf1c, const float* __restrict__ bf2c,
    const float* __restrict__ scl, float* __restrict__ out, int B) {
    __shared__ float smh[2048 + 4096 + 344];
    float* a5s = smh;          // 8 x 256
    float* f1s = smh + 2048;   // 8 x 512
    float* lg = smh + 6144;    // 8 x 43
    int t = threadIdx.x;
    int img0 = blockIdx.x * 8;
    const float* src = g_a5 + (size_t)img0 * 256;
    for (int i = t; i < 2048; i += 256) a5s[i] = src[i];
    __syncthreads();

    // fc1 (k ascending)
    {
        const float4* a5s4 = (const float4*)a5s;  // [8][64]
        float s_out = scl[5];
#pragma unroll
        for (int rep = 0; rep < 2; rep++) {
            int n = t + rep * 256;
            float acc[8];
#pragma unroll
            for (int im = 0; im < 8; im++) acc[im] = 0.f;
#pragma unroll 4
            for (int k4 = 0; k4 < 64; k4++) {
                float4 wv = __ldg(&g_wf1q4[k4 * 512 + n]);
#pragma unroll
                for (int im = 0; im < 8; im++) {
                    float4 xv = a5s4[im * 64 + k4];
                    FMA4(acc[im], xv, wv);
                }
            }
            float b = __ldg(bf1c + n);
#pragma unroll
            for (int im = 0; im < 8; im++) {
                float y = __fadd_rn(acc[im], b);
                f1s[im * 512 + n] = qval_relu(y, s_out);
            }
        }
    }
    __syncthreads();

    // fc2 + quant_identity
    {
        const float4* f1s4 = (const float4*)f1s;  // [8][128]
        float s_out = scl[6];
        if (t < 172) {
            int n = t >> 2, pair = t & 3;
            float a0 = 0.f, a1 = 0.f;
#pragma unroll 4
            for (int k4 = 0; k4 < 128; k4++) {
                float4 wv = __ldg(&g_wf2q4[k4 * 43 + n]);
                float4 x0 = f1s4[(pair * 2) * 128 + k4];
                float4 x1 = f1s4[(pair * 2 + 1) * 128 + k4];
                FMA4(a0, x0, wv);
                FMA4(a1, x1, wv);
            }
            float b = __ldg(bf2c + n);
            lg[(pair * 2) * 43 + n] = qval_id(__fadd_rn(a0, b), s_out);
            lg[(pair * 2 + 1) * 43 + n] = qval_id(__fadd_rn(a1, b), s_out);
        }
    }
    __syncthreads();

    // softmax (43 classes, one warp per image)
    {
        int lane = t & 31, w = t >> 5;
        float v0 = lg[w * 43 + lane];
        float v1 = (lane < 11) ? lg[w * 43 + 32 + lane] : -INFINITY;
        float mx = fmaxf(v0, v1);
#pragma unroll
        for (int o = 16; o > 0; o >>= 1) mx = fmaxf(mx, __shfl_xor_sync(0xffffffffu, mx, o));
        float e0 = expf(v0 - mx);
        float e1 = (lane < 11) ? expf(v1 - mx) : 0.f;
        float sum = e0 + e1;
#pragma unroll
        for (int o = 16; o > 0; o >>= 1) sum += __shfl_xor_sync(0xffffffffu, sum, o);
        if ((img0 + w) < B) {
            out[(size_t)(img0 + w) * 43 + lane] = __fdiv_rn(e0, sum);
            if (lane < 11)
                out[(size_t)(img0 + w) * 43 + 32 + lane] = __fdiv_rn(e1, sum);
        }
    }
}

// ---------------------------------------------------------------------------
extern "C" void kernel_launch(void* const* d_in, const int* in_sizes, int n_in,
                              void* d_out, int out_size) {
    const float *x = 0, *w1 = 0, *b1 = 0, *w2 = 0, *b2 = 0, *w3 = 0, *b3 = 0;
    const float *w4 = 0, *b4 = 0, *w5 = 0, *b5 = 0, *wf1 = 0, *bf1 = 0;
    const float *wf2 = 0, *bf2 = 0, *scl = 0;
    int B = 2048;
    for (int i = 0; i < n_in; i++) {
        const float* p = (const float*)d_in[i];
        switch (in_sizes[i]) {
            case 432:    w1 = p;  break;
            case 16:     b1 = p;  break;
            case 4608:   w2 = p;  break;
            case 32:     b2 = p;  break;
            case 18432:  w3 = p;  break;
            case 64:     b3 = p;  break;
            case 73728:  w4 = p;  break;
            case 128:    b4 = p;  break;
            case 294912: w5 = p;  break;
            case 256:    b5 = p;  break;
            case 131072: wf1 = p; break;
            case 512:    bf1 = p; break;
            case 22016:  wf2 = p; break;
            case 43:     bf2 = p; break;
            case 7:      scl = p; break;
            default:     x = p; B = in_sizes[i] / 3072; break;
        }
    }
    float* out = (float*)d_out;

    quant_weights_kernel<<<7, 256>>>(w1, w2, w3, w4, w5, wf1, wf2);
    conv1_kernel<<<B, 256>>>(x, b1, scl);
    conv2_kernel<<<B / 2, 256>>>(b2, scl);
    conv3_kernel<<<B / 4, 256>>>(b3, scl);
    conv4_kernel<<<B / 8, 256>>>(b4, scl);
    conv5_kernel<<<B / 8, 256>>>(b5, scl);
    head_kernel<<<B / 8, 256>>>(bf1, bf2, scl, out, B);
}